// round 1
// baseline (speedup 1.0000x reference)
#include <cuda_runtime.h>
#include <cuda_bf16.h>
#include <math.h>

// ---------------- problem constants ----------------
#define BATCH   16
#define HH      56
#define WW      56
#define DIM     384
#define HID     1536
#define WS      7
#define NWIN    1024            // 16 * 8 * 8
#define TSEQ    49              // 7*7
#define MTOK    50176           // 16*56*56 == NWIN*TSEQ
#define LN_EPS  1e-5f

// ---------------- device scratch (no mallocs allowed) ----------------
__device__ float g_xw [ (size_t)MTOK * DIM ];   // LN1 output, window layout (n*49+t, c)
__device__ float g_xB [ (size_t)MTOK * DIM ];   // xw @ Bm
__device__ float g_h  [ (size_t)MTOK * DIM ];   // scan states, window layout
__device__ float g_xr [ (size_t)MTOK * DIM ];   // mamba out, image layout
__device__ float g_ln2[ (size_t)MTOK * DIM ];   // LN2(xr)
__device__ float g_hid[ (size_t)MTOK * HID ];   // gelu(ln2 @ W1 + b1)

// ---------------- LayerNorm (warp per token), optional window remap ----------------
__global__ __launch_bounds__(256)
void ln_kernel(const float* __restrict__ x, const float* __restrict__ gw,
               const float* __restrict__ gb, float* __restrict__ out, int remap)
{
    const int warp = threadIdx.x >> 5;
    const int lane = threadIdx.x & 31;
    const int token = blockIdx.x * 8 + warp;          // MTOK divisible by 8

    const float4* row = reinterpret_cast<const float4*>(x + (size_t)token * DIM);
    float4 v[3];
    float sum = 0.f, sq = 0.f;
#pragma unroll
    for (int q = 0; q < 3; q++) {
        v[q] = row[lane + 32 * q];
        sum += v[q].x + v[q].y + v[q].z + v[q].w;
        sq  += v[q].x * v[q].x + v[q].y * v[q].y + v[q].z * v[q].z + v[q].w * v[q].w;
    }
#pragma unroll
    for (int o = 16; o > 0; o >>= 1) {
        sum += __shfl_xor_sync(0xffffffffu, sum, o);
        sq  += __shfl_xor_sync(0xffffffffu, sq, o);
    }
    const float mu  = sum * (1.f / DIM);
    const float inv = rsqrtf(sq * (1.f / DIM) - mu * mu + LN_EPS);

    int orow = token;
    if (remap) {
        // image token (b, h, w)  ->  window row n*49 + t
        const int b   = token / (HH * WW);
        const int rem = token - b * (HH * WW);
        const int h   = rem / WW;
        const int w   = rem - h * WW;
        const int n   = b * 64 + (h / WS) * 8 + (w / WS);
        const int t   = (h % WS) * WS + (w % WS);
        orow = n * TSEQ + t;
    }
    float4* orowp = reinterpret_cast<float4*>(out + (size_t)orow * DIM);
    const float4* gw4 = reinterpret_cast<const float4*>(gw);
    const float4* gb4 = reinterpret_cast<const float4*>(gb);
#pragma unroll
    for (int q = 0; q < 3; q++) {
        const int c4 = lane + 32 * q;
        const float4 wv = gw4[c4];
        const float4 bv = gb4[c4];
        float4 r;
        r.x = (v[q].x - mu) * inv * wv.x + bv.x;
        r.y = (v[q].y - mu) * inv * wv.y + bv.y;
        r.z = (v[q].z - mu) * inv * wv.z + bv.z;
        r.w = (v[q].w - mu) * inv * wv.w + bv.w;
        orowp[c4] = r;
    }
}

// ---------------- sequential scan: h_t = xB_t + h_{t-1} @ A ----------------
// 128 blocks x 8 windows, 384 threads (thread = one output column c).
// h kept in SMEM transposed as shT[k][w] so the k-loop reads 2 broadcast LDS.128.
__global__ __launch_bounds__(384)
void scan_kernel(const float* __restrict__ xB, const float* __restrict__ A,
                 float* __restrict__ hout)
{
    __shared__ __align__(16) float shT[DIM * 8];   // [k][w], 12 KB
    const int c  = threadIdx.x;
    const int n0 = blockIdx.x * 8;

#pragma unroll
    for (int w = 0; w < 8; w++) shT[c * 8 + w] = 0.f;
    __syncthreads();

    const float* Ap = A + c;   // A[k*DIM + c]

    for (int t = 0; t < TSEQ; t++) {
        float acc[8];
#pragma unroll
        for (int w = 0; w < 8; w++)
            acc[w] = xB[((size_t)(n0 + w) * TSEQ + t) * DIM + c];

        if (t > 0) {
#pragma unroll 8
            for (int k = 0; k < DIM; k++) {
                const float a = Ap[(size_t)k * DIM];
                const float4 h0 = *reinterpret_cast<const float4*>(&shT[k * 8]);
                const float4 h1 = *reinterpret_cast<const float4*>(&shT[k * 8 + 4]);
                acc[0] = fmaf(h0.x, a, acc[0]);
                acc[1] = fmaf(h0.y, a, acc[1]);
                acc[2] = fmaf(h0.z, a, acc[2]);
                acc[3] = fmaf(h0.w, a, acc[3]);
                acc[4] = fmaf(h1.x, a, acc[4]);
                acc[5] = fmaf(h1.y, a, acc[5]);
                acc[6] = fmaf(h1.z, a, acc[6]);
                acc[7] = fmaf(h1.w, a, acc[7]);
            }
        }
        __syncthreads();
        *reinterpret_cast<float4*>(&shT[c * 8])     = make_float4(acc[0], acc[1], acc[2], acc[3]);
        *reinterpret_cast<float4*>(&shT[c * 8 + 4]) = make_float4(acc[4], acc[5], acc[6], acc[7]);
#pragma unroll
        for (int w = 0; w < 8; w++)
            hout[((size_t)(n0 + w) * TSEQ + t) * DIM + c] = acc[w];
        __syncthreads();
    }
}

// ---------------- fp32 GEMM 128x128x8, 256 threads, 8x8 microtile ----------------
#define EPI_NONE    0
#define EPI_WINREV  1
#define EPI_GELU    2
#define EPI_BIASRES 3

#define BM 128
#define BN 128
#define BK 8

__device__ __forceinline__ float gelu_exact(float v)
{
    return 0.5f * v * (1.f + erff(v * 0.70710678118654752f));
}

template<int EPI>
__global__ __launch_bounds__(256)
void gemm_f32(const float* __restrict__ A, const float* __restrict__ B,
              const float* __restrict__ bias, const float* __restrict__ res,
              float* __restrict__ C, int M, int N, int K)
{
    __shared__ __align__(16) float As[2][BK][BM];
    __shared__ __align__(16) float Bs[2][BK][BN];

    const int tid = threadIdx.x;
    const int m0 = blockIdx.y * BM;
    const int n0 = blockIdx.x * BN;

    const int arow = tid >> 1;            // 0..127
    const int akq  = (tid & 1) * 4;       // k offset (0 or 4)
    const int bkr  = tid >> 5;            // 0..7
    const int bnq  = (tid & 31) * 4;      // 0..124
    const int tx = tid & 15, ty = tid >> 4;

    float acc[8][8];
#pragma unroll
    for (int i = 0; i < 8; i++)
#pragma unroll
        for (int j = 0; j < 8; j++) acc[i][j] = 0.f;

    const float* Aptr = A + (size_t)(m0 + arow) * K + akq;
    const float* Bptr = B + (size_t)bkr * N + n0 + bnq;

    float4 aReg = *reinterpret_cast<const float4*>(Aptr);
    float4 bReg = *reinterpret_cast<const float4*>(Bptr);
    As[0][akq + 0][arow] = aReg.x;
    As[0][akq + 1][arow] = aReg.y;
    As[0][akq + 2][arow] = aReg.z;
    As[0][akq + 3][arow] = aReg.w;
    *reinterpret_cast<float4*>(&Bs[0][bkr][bnq]) = bReg;
    __syncthreads();

    const int nk = K / BK;
    for (int kt = 0; kt < nk; kt++) {
        const int cur = kt & 1, nxt = cur ^ 1;
        if (kt + 1 < nk) {
            aReg = *reinterpret_cast<const float4*>(Aptr + (kt + 1) * BK);
            bReg = *reinterpret_cast<const float4*>(Bptr + (size_t)(kt + 1) * BK * N);
        }
#pragma unroll
        for (int k = 0; k < BK; k++) {
            const float4 a0 = *reinterpret_cast<const float4*>(&As[cur][k][ty * 4]);
            const float4 a1 = *reinterpret_cast<const float4*>(&As[cur][k][64 + ty * 4]);
            const float4 b0 = *reinterpret_cast<const float4*>(&Bs[cur][k][tx * 4]);
            const float4 b1 = *reinterpret_cast<const float4*>(&Bs[cur][k][64 + tx * 4]);
            const float av[8] = {a0.x, a0.y, a0.z, a0.w, a1.x, a1.y, a1.z, a1.w};
            const float bv[8] = {b0.x, b0.y, b0.z, b0.w, b1.x, b1.y, b1.z, b1.w};
#pragma unroll
            for (int i = 0; i < 8; i++)
#pragma unroll
                for (int j = 0; j < 8; j++)
                    acc[i][j] = fmaf(av[i], bv[j], acc[i][j]);
        }
        if (kt + 1 < nk) {
            As[nxt][akq + 0][arow] = aReg.x;
            As[nxt][akq + 1][arow] = aReg.y;
            As[nxt][akq + 2][arow] = aReg.z;
            As[nxt][akq + 3][arow] = aReg.w;
            *reinterpret_cast<float4*>(&Bs[nxt][bkr][bnq]) = bReg;
        }
        __syncthreads();
    }

    // ---------------- epilogue ----------------
    float4 bias0 = make_float4(0.f, 0.f, 0.f, 0.f), bias1 = bias0;
    if (EPI == EPI_GELU || EPI == EPI_BIASRES) {
        bias0 = *reinterpret_cast<const float4*>(bias + n0 + tx * 4);
        bias1 = *reinterpret_cast<const float4*>(bias + n0 + 64 + tx * 4);
    }

#pragma unroll
    for (int i = 0; i < 8; i++) {
        const int lrow = ty * 4 + (i & 3) + ((i >> 2) << 6);
        int gm = m0 + lrow;
        int orow = gm;
        if (EPI == EPI_WINREV) {
            const int n = gm / TSEQ;
            const int t = gm - n * TSEQ;
            const int b = n >> 6;
            const int rm = n & 63;
            const int wh = rm >> 3, wwi = rm & 7;
            const int ti = t / WS, tj = t - ti * WS;
            orow = (b * HH + wh * WS + ti) * WW + wwi * WS + tj;
        }
        float4 v0 = make_float4(acc[i][0], acc[i][1], acc[i][2], acc[i][3]);
        float4 v1 = make_float4(acc[i][4], acc[i][5], acc[i][6], acc[i][7]);
        if (EPI == EPI_GELU) {
            v0.x = gelu_exact(v0.x + bias0.x); v0.y = gelu_exact(v0.y + bias0.y);
            v0.z = gelu_exact(v0.z + bias0.z); v0.w = gelu_exact(v0.w + bias0.w);
            v1.x = gelu_exact(v1.x + bias1.x); v1.y = gelu_exact(v1.y + bias1.y);
            v1.z = gelu_exact(v1.z + bias1.z); v1.w = gelu_exact(v1.w + bias1.w);
        }
        if (EPI == EPI_BIASRES) {
            const float4 r0 = *reinterpret_cast<const float4*>(res + (size_t)gm * N + n0 + tx * 4);
            const float4 r1 = *reinterpret_cast<const float4*>(res + (size_t)gm * N + n0 + 64 + tx * 4);
            v0.x += bias0.x + r0.x; v0.y += bias0.y + r0.y;
            v0.z += bias0.z + r0.z; v0.w += bias0.w + r0.w;
            v1.x += bias1.x + r1.x; v1.y += bias1.y + r1.y;
            v1.z += bias1.z + r1.z; v1.w += bias1.w + r1.w;
        }
        *reinterpret_cast<float4*>(C + (size_t)orow * N + n0 + tx * 4)      = v0;
        *reinterpret_cast<float4*>(C + (size_t)orow * N + n0 + 64 + tx * 4) = v1;
    }
}

// ---------------- launch ----------------
extern "C" void kernel_launch(void* const* d_in, const int* in_sizes, int n_in,
                              void* d_out, int out_size)
{
    const float* x    = (const float*)d_in[0];
    const float* A    = (const float*)d_in[1];
    const float* Bm   = (const float*)d_in[2];
    const float* Cm   = (const float*)d_in[3];
    const float* ln1w = (const float*)d_in[4];
    const float* ln1b = (const float*)d_in[5];
    const float* ln2w = (const float*)d_in[6];
    const float* ln2b = (const float*)d_in[7];
    const float* W1   = (const float*)d_in[8];
    const float* b1   = (const float*)d_in[9];
    const float* W2   = (const float*)d_in[10];
    const float* b2   = (const float*)d_in[11];
    float* out = (float*)d_out;

    float *p_xw, *p_xB, *p_h, *p_xr, *p_ln2, *p_hid;
    cudaGetSymbolAddress((void**)&p_xw,  g_xw);
    cudaGetSymbolAddress((void**)&p_xB,  g_xB);
    cudaGetSymbolAddress((void**)&p_h,   g_h);
    cudaGetSymbolAddress((void**)&p_xr,  g_xr);
    cudaGetSymbolAddress((void**)&p_ln2, g_ln2);
    cudaGetSymbolAddress((void**)&p_hid, g_hid);

    // 1. LN1 + window partition: x -> g_xw (window layout)
    ln_kernel<<<MTOK / 8, 256>>>(x, ln1w, ln1b, p_xw, 1);

    // 2. xB = xw @ Bm
    {
        dim3 g(DIM / BN, MTOK / BM);
        gemm_f32<EPI_NONE><<<g, 256>>>(p_xw, Bm, nullptr, nullptr, p_xB, MTOK, DIM, DIM);
    }

    // 3. sequential scan over T=49
    scan_kernel<<<NWIN / 8, 384>>>(p_xB, A, p_h);

    // 4. out = h @ Cm, fused window-reverse -> g_xr (image layout)
    {
        dim3 g(DIM / BN, MTOK / BM);
        gemm_f32<EPI_WINREV><<<g, 256>>>(p_h, Cm, nullptr, nullptr, p_xr, MTOK, DIM, DIM);
    }

    // 5. LN2
    ln_kernel<<<MTOK / 8, 256>>>(p_xr, ln2w, ln2b, p_ln2, 0);

    // 6. hid = gelu(ln2 @ W1 + b1)
    {
        dim3 g(HID / BN, MTOK / BM);
        gemm_f32<EPI_GELU><<<g, 256>>>(p_ln2, W1, b1, nullptr, p_hid, MTOK, HID, DIM);
    }

    // 7. out = xr + hid @ W2 + b2
    {
        dim3 g(DIM / BN, MTOK / BM);
        gemm_f32<EPI_BIASRES><<<g, 256>>>(p_hid, W2, b2, p_xr, out, MTOK, DIM, HID);
    }
}

// round 3
// speedup vs baseline: 4.1609x; 4.1609x over previous
#include <cuda_runtime.h>
#include <cuda_fp16.h>
#include <cstdint>
#include <math.h>

// ---------------- problem constants ----------------
#define BATCH   16
#define HH      56
#define WW      56
#define DIM     384
#define HID     1536
#define WS      7
#define NWIN    1024
#define TSEQ    49
#define MTOK    50176
#define LN_EPS  1e-5f

// ---------------- device scratch ----------------
__device__ float  g_xB  [ (size_t)MTOK * DIM ];   // xw @ Bm (fp32, scan input)
__device__ float  g_xr  [ (size_t)MTOK * DIM ];   // mamba out, image layout (fp32: LN2 + residual)
__device__ __half g_xwh [ (size_t)MTOK * DIM ];   // LN1 out, window layout (half)
__device__ __half g_hh  [ (size_t)MTOK * DIM ];   // scan states (half)
__device__ __half g_l2h [ (size_t)MTOK * DIM ];   // LN2 out (half)
__device__ __half g_hidh[ (size_t)MTOK * HID ];   // gelu(ln2@W1+b1) (half)
__device__ __half g_Bmt [ DIM * DIM ];            // Bm^T  [N][K] half
__device__ __half g_Cmt [ DIM * DIM ];            // Cm^T
__device__ __half g_W1t [ (size_t)HID * DIM ];    // W1^T [1536][384]
__device__ __half g_W2t [ (size_t)DIM * HID ];    // W2^T [384][1536]

// ---------------- transpose + fp32->fp16 for weights ----------------
__global__ __launch_bounds__(256)
void transpose_h(const float* __restrict__ W, __half* __restrict__ Wt, int K, int N)
{
    __shared__ float tile[32][33];
    const int k0 = blockIdx.y * 32, n0 = blockIdx.x * 32;
    const int tx = threadIdx.x & 31, ty = threadIdx.x >> 5;   // 32 x 8
#pragma unroll
    for (int i = 0; i < 32; i += 8)
        tile[ty + i][tx] = W[(size_t)(k0 + ty + i) * N + n0 + tx];
    __syncthreads();
#pragma unroll
    for (int i = 0; i < 32; i += 8)
        Wt[(size_t)(n0 + ty + i) * K + k0 + tx] = __float2half_rn(tile[tx][ty + i]);
}

// ---------------- LayerNorm (warp per token) -> half, optional window remap ----------------
__global__ __launch_bounds__(256)
void ln_kernel(const float* __restrict__ x, const float* __restrict__ gw,
               const float* __restrict__ gb, __half* __restrict__ out, int remap)
{
    const int warp = threadIdx.x >> 5;
    const int lane = threadIdx.x & 31;
    const int token = blockIdx.x * 8 + warp;

    const float4* row = reinterpret_cast<const float4*>(x + (size_t)token * DIM);
    float4 v[3];
    float sum = 0.f, sq = 0.f;
#pragma unroll
    for (int q = 0; q < 3; q++) {
        v[q] = row[lane + 32 * q];
        sum += v[q].x + v[q].y + v[q].z + v[q].w;
        sq  += v[q].x * v[q].x + v[q].y * v[q].y + v[q].z * v[q].z + v[q].w * v[q].w;
    }
#pragma unroll
    for (int o = 16; o > 0; o >>= 1) {
        sum += __shfl_xor_sync(0xffffffffu, sum, o);
        sq  += __shfl_xor_sync(0xffffffffu, sq, o);
    }
    const float mu  = sum * (1.f / DIM);
    const float inv = rsqrtf(sq * (1.f / DIM) - mu * mu + LN_EPS);

    int orow = token;
    if (remap) {
        const int b   = token / (HH * WW);
        const int rem = token - b * (HH * WW);
        const int h   = rem / WW;
        const int w   = rem - h * WW;
        const int n   = b * 64 + (h / WS) * 8 + (w / WS);
        const int t   = (h % WS) * WS + (w % WS);
        orow = n * TSEQ + t;
    }
    __half* op = out + (size_t)orow * DIM;
    const float4* gw4 = reinterpret_cast<const float4*>(gw);
    const float4* gb4 = reinterpret_cast<const float4*>(gb);
#pragma unroll
    for (int q = 0; q < 3; q++) {
        const int c4 = lane + 32 * q;
        const float4 wv = gw4[c4];
        const float4 bv = gb4[c4];
        float rx = (v[q].x - mu) * inv * wv.x + bv.x;
        float ry = (v[q].y - mu) * inv * wv.y + bv.y;
        float rz = (v[q].z - mu) * inv * wv.z + bv.z;
        float rw = (v[q].w - mu) * inv * wv.w + bv.w;
        *reinterpret_cast<__half2*>(op + c4 * 4)     = __floats2half2_rn(rx, ry);
        *reinterpret_cast<__half2*>(op + c4 * 4 + 2) = __floats2half2_rn(rz, rw);
    }
}

// ---------------- sequential scan: h_t = xB_t + h_{t-1} @ A  (fp32, half out) ----------------
__global__ __launch_bounds__(384)
void scan_kernel(const float* __restrict__ xB, const float* __restrict__ A,
                 __half* __restrict__ hout)
{
    __shared__ __align__(16) float shT[DIM * 8];
    const int c  = threadIdx.x;
    const int n0 = blockIdx.x * 8;

#pragma unroll
    for (int w = 0; w < 8; w++) shT[c * 8 + w] = 0.f;
    __syncthreads();

    const float* Ap = A + c;

    for (int t = 0; t < TSEQ; t++) {
        float acc[8];
#pragma unroll
        for (int w = 0; w < 8; w++)
            acc[w] = xB[((size_t)(n0 + w) * TSEQ + t) * DIM + c];

        if (t > 0) {
#pragma unroll 8
            for (int k = 0; k < DIM; k++) {
                const float a = Ap[(size_t)k * DIM];
                const float4 h0 = *reinterpret_cast<const float4*>(&shT[k * 8]);
                const float4 h1 = *reinterpret_cast<const float4*>(&shT[k * 8 + 4]);
                acc[0] = fmaf(h0.x, a, acc[0]);
                acc[1] = fmaf(h0.y, a, acc[1]);
                acc[2] = fmaf(h0.z, a, acc[2]);
                acc[3] = fmaf(h0.w, a, acc[3]);
                acc[4] = fmaf(h1.x, a, acc[4]);
                acc[5] = fmaf(h1.y, a, acc[5]);
                acc[6] = fmaf(h1.z, a, acc[6]);
                acc[7] = fmaf(h1.w, a, acc[7]);
            }
        }
        __syncthreads();
        *reinterpret_cast<float4*>(&shT[c * 8])     = make_float4(acc[0], acc[1], acc[2], acc[3]);
        *reinterpret_cast<float4*>(&shT[c * 8 + 4]) = make_float4(acc[4], acc[5], acc[6], acc[7]);
#pragma unroll
        for (int w = 0; w < 8; w++)
            hout[((size_t)(n0 + w) * TSEQ + t) * DIM + c] = __float2half_rn(acc[w]);
        __syncthreads();
    }
}

// ---------------- fp16 tensor-core GEMM: C[M,N] = A[M,K] @ Bt[N,K]^T ----------------
#define EPI_NONE    0
#define EPI_WINREV  1
#define EPI_GELU    2
#define EPI_BIASRES 3

#define PADH  40            // halfs per smem row (conflict-free for ldmatrix)
#define ASTRH (128 * PADH)  // halfs per smem buffer

__device__ __forceinline__ float gelu_exact(float v)
{
    return 0.5f * v * (1.f + erff(v * 0.70710678118654752f));
}

__device__ __forceinline__ void ldsm_x4(uint32_t& r0, uint32_t& r1, uint32_t& r2, uint32_t& r3, uint32_t addr)
{
    asm volatile("ldmatrix.sync.aligned.m8n8.x4.shared.b16 {%0,%1,%2,%3}, [%4];"
                 : "=r"(r0), "=r"(r1), "=r"(r2), "=r"(r3) : "r"(addr));
}
__device__ __forceinline__ void ldsm_x2(uint32_t& r0, uint32_t& r1, uint32_t addr)
{
    asm volatile("ldmatrix.sync.aligned.m8n8.x2.shared.b16 {%0,%1}, [%2];"
                 : "=r"(r0), "=r"(r1) : "r"(addr));
}
__device__ __forceinline__ void mma16816(float& c0, float& c1, float& c2, float& c3,
                                         uint32_t a0, uint32_t a1, uint32_t a2, uint32_t a3,
                                         uint32_t b0, uint32_t b1)
{
    asm volatile("mma.sync.aligned.m16n8k16.row.col.f32.f16.f16.f32 "
                 "{%0,%1,%2,%3}, {%4,%5,%6,%7}, {%8,%9}, {%0,%1,%2,%3};"
                 : "+f"(c0), "+f"(c1), "+f"(c2), "+f"(c3)
                 : "r"(a0), "r"(a1), "r"(a2), "r"(a3), "r"(b0), "r"(b1));
}

template<int EPI>
__global__ __launch_bounds__(256)
void gemm_h(const __half* __restrict__ Ag, const __half* __restrict__ Bg,
            const float* __restrict__ bias, const float* __restrict__ res,
            void* __restrict__ Cv, int M, int N, int K)
{
    __shared__ __align__(16) __half As[2][ASTRH];
    __shared__ __align__(16) __half Bs[2][ASTRH];

    const int tid  = threadIdx.x;
    const int lane = tid & 31;
    const int wid  = tid >> 5;
    const int wm   = wid >> 1;          // 0..3
    const int wn   = wid & 1;           // 0..1
    const int m0   = blockIdx.y * 128;
    const int n0   = blockIdx.x * 128;

    // global staging: 512 chunks of 8 halfs per operand per k-tile; thread owns 2
    const int c0r = tid >> 2,         c0o = (tid & 3) * 8;
    const int c1r = (tid + 256) >> 2, c1o = ((tid + 256) & 3) * 8;
    const __half* Ap0 = Ag + (size_t)(m0 + c0r) * K + c0o;
    const __half* Ap1 = Ag + (size_t)(m0 + c1r) * K + c1o;
    const __half* Bp0 = Bg + (size_t)(n0 + c0r) * K + c0o;
    const __half* Bp1 = Bg + (size_t)(n0 + c1r) * K + c1o;
    const int sa0 = c0r * PADH + c0o;
    const int sa1 = c1r * PADH + c1o;

    const uint32_t asB = (uint32_t)__cvta_generic_to_shared(&As[0][0]);
    const uint32_t bsB = (uint32_t)__cvta_generic_to_shared(&Bs[0][0]);

    // ldmatrix lane addresses (byte offsets)
    const int l7 = lane & 7;
    const uint32_t aOff = (uint32_t)(((wm * 32 + ((lane >> 3) & 1) * 8 + l7) * PADH + (lane >> 4) * 8) * 2);
    const int bl = lane & 15;
    const uint32_t bOff = (uint32_t)(((wn * 64 + (bl & 7)) * PADH + (bl >> 3) * 8) * 2);

    float acc[2][8][4];
#pragma unroll
    for (int mi = 0; mi < 2; mi++)
#pragma unroll
        for (int ni = 0; ni < 8; ni++)
#pragma unroll
            for (int q = 0; q < 4; q++) acc[mi][ni][q] = 0.f;

    int4 pa0 = *reinterpret_cast<const int4*>(Ap0);
    int4 pa1 = *reinterpret_cast<const int4*>(Ap1);
    int4 pb0 = *reinterpret_cast<const int4*>(Bp0);
    int4 pb1 = *reinterpret_cast<const int4*>(Bp1);
    *reinterpret_cast<int4*>(&As[0][sa0]) = pa0;
    *reinterpret_cast<int4*>(&As[0][sa1]) = pa1;
    *reinterpret_cast<int4*>(&Bs[0][sa0]) = pb0;
    *reinterpret_cast<int4*>(&Bs[0][sa1]) = pb1;
    __syncthreads();

    const int nk = K >> 5;
    for (int kt = 0; kt < nk; kt++) {
        const int buf = kt & 1;
        if (kt + 1 < nk) {
            pa0 = *reinterpret_cast<const int4*>(Ap0 + (kt + 1) * 32);
            pa1 = *reinterpret_cast<const int4*>(Ap1 + (kt + 1) * 32);
            pb0 = *reinterpret_cast<const int4*>(Bp0 + (kt + 1) * 32);
            pb1 = *reinterpret_cast<const int4*>(Bp1 + (kt + 1) * 32);
        }
        const uint32_t aB = asB + buf * (ASTRH * 2) + aOff;
        const uint32_t bB = bsB + buf * (ASTRH * 2) + bOff;
#pragma unroll
        for (int kk = 0; kk < 2; kk++) {
            uint32_t a[2][4], bf[8][2];
            ldsm_x4(a[0][0], a[0][1], a[0][2], a[0][3], aB + kk * 32);
            ldsm_x4(a[1][0], a[1][1], a[1][2], a[1][3], aB + kk * 32 + 16 * PADH * 2);
#pragma unroll
            for (int ni = 0; ni < 8; ni++)
                ldsm_x2(bf[ni][0], bf[ni][1], bB + kk * 32 + ni * 8 * PADH * 2);
#pragma unroll
            for (int mi = 0; mi < 2; mi++)
#pragma unroll
                for (int ni = 0; ni < 8; ni++)
                    mma16816(acc[mi][ni][0], acc[mi][ni][1], acc[mi][ni][2], acc[mi][ni][3],
                             a[mi][0], a[mi][1], a[mi][2], a[mi][3], bf[ni][0], bf[ni][1]);
        }
        if (kt + 1 < nk) {
            const int nb = buf ^ 1;
            *reinterpret_cast<int4*>(&As[nb][sa0]) = pa0;
            *reinterpret_cast<int4*>(&As[nb][sa1]) = pa1;
            *reinterpret_cast<int4*>(&Bs[nb][sa0]) = pb0;
            *reinterpret_cast<int4*>(&Bs[nb][sa1]) = pb1;
        }
        __syncthreads();
    }

    // ---------------- epilogue ----------------
    const int gr = lane >> 2, tg = lane & 3;

    float2 bias2[8];
    if (EPI == EPI_GELU || EPI == EPI_BIASRES) {
#pragma unroll
        for (int ni = 0; ni < 8; ni++)
            bias2[ni] = *reinterpret_cast<const float2*>(bias + n0 + wn * 64 + ni * 8 + tg * 2);
    }

#pragma unroll
    for (int mi = 0; mi < 2; mi++)
#pragma unroll
    for (int rh = 0; rh < 2; rh++) {
        const int gm = m0 + wm * 32 + mi * 16 + rh * 8 + gr;
        int orow = gm;
        if (EPI == EPI_WINREV) {
            const int n = gm / TSEQ;
            const int t = gm - n * TSEQ;
            const int b = n >> 6;
            const int rm = n & 63;
            const int wh = rm >> 3, wwi = rm & 7;
            const int ti = t / WS, tj = t - ti * WS;
            orow = (b * HH + wh * WS + ti) * WW + wwi * WS + tj;
        }
#pragma unroll
        for (int ni = 0; ni < 8; ni++) {
            const int col = n0 + wn * 64 + ni * 8 + tg * 2;
            float v0 = acc[mi][ni][rh * 2];
            float v1 = acc[mi][ni][rh * 2 + 1];
            if (EPI == EPI_GELU) {
                v0 = gelu_exact(v0 + bias2[ni].x);
                v1 = gelu_exact(v1 + bias2[ni].y);
                __half* C = (__half*)Cv;
                *reinterpret_cast<__half2*>(C + (size_t)orow * N + col) = __floats2half2_rn(v0, v1);
            } else {
                if (EPI == EPI_BIASRES) {
                    const float2 r = *reinterpret_cast<const float2*>(res + (size_t)gm * N + col);
                    v0 += bias2[ni].x + r.x;
                    v1 += bias2[ni].y + r.y;
                }
                float* C = (float*)Cv;
                float2 o; o.x = v0; o.y = v1;
                *reinterpret_cast<float2*>(C + (size_t)orow * N + col) = o;
            }
        }
    }
}

// ---------------- launch ----------------
extern "C" void kernel_launch(void* const* d_in, const int* in_sizes, int n_in,
                              void* d_out, int out_size)
{
    const float* x    = (const float*)d_in[0];
    const float* A    = (const float*)d_in[1];
    const float* Bm   = (const float*)d_in[2];
    const float* Cm   = (const float*)d_in[3];
    const float* ln1w = (const float*)d_in[4];
    const float* ln1b = (const float*)d_in[5];
    const float* ln2w = (const float*)d_in[6];
    const float* ln2b = (const float*)d_in[7];
    const float* W1   = (const float*)d_in[8];
    const float* b1   = (const float*)d_in[9];
    const float* W2   = (const float*)d_in[10];
    const float* b2   = (const float*)d_in[11];
    float* out = (float*)d_out;

    float  *p_xB, *p_xr;
    __half *p_xwh, *p_hh, *p_l2h, *p_hidh, *p_Bmt, *p_Cmt, *p_W1t, *p_W2t;
    cudaGetSymbolAddress((void**)&p_xB,   g_xB);
    cudaGetSymbolAddress((void**)&p_xr,   g_xr);
    cudaGetSymbolAddress((void**)&p_xwh,  g_xwh);
    cudaGetSymbolAddress((void**)&p_hh,   g_hh);
    cudaGetSymbolAddress((void**)&p_l2h,  g_l2h);
    cudaGetSymbolAddress((void**)&p_hidh, g_hidh);
    cudaGetSymbolAddress((void**)&p_Bmt,  g_Bmt);
    cudaGetSymbolAddress((void**)&p_Cmt,  g_Cmt);
    cudaGetSymbolAddress((void**)&p_W1t,  g_W1t);
    cudaGetSymbolAddress((void**)&p_W2t,  g_W2t);

    // 0. weight transposes -> half [N][K]
    transpose_h<<<dim3(DIM / 32, DIM / 32), 256>>>(Bm, p_Bmt, DIM, DIM);
    transpose_h<<<dim3(DIM / 32, DIM / 32), 256>>>(Cm, p_Cmt, DIM, DIM);
    transpose_h<<<dim3(HID / 32, DIM / 32), 256>>>(W1, p_W1t, DIM, HID);
    transpose_h<<<dim3(DIM / 32, HID / 32), 256>>>(W2, p_W2t, HID, DIM);

    // 1. LN1 + window partition -> half
    ln_kernel<<<MTOK / 8, 256>>>(x, ln1w, ln1b, p_xwh, 1);

    // 2. xB = xw @ Bm  (fp32 out, scan input)
    gemm_h<EPI_NONE><<<dim3(DIM / 128, MTOK / 128), 256>>>(p_xwh, p_Bmt, nullptr, nullptr, p_xB, MTOK, DIM, DIM);

    // 3. sequential scan, half out
    scan_kernel<<<NWIN / 8, 384>>>(p_xB, A, p_hh);

    // 4. xr = h @ Cm, fused window-reverse (fp32 out)
    gemm_h<EPI_WINREV><<<dim3(DIM / 128, MTOK / 128), 256>>>(p_hh, p_Cmt, nullptr, nullptr, p_xr, MTOK, DIM, DIM);

    // 5. LN2 -> half
    ln_kernel<<<MTOK / 8, 256>>>(p_xr, ln2w, ln2b, p_l2h, 0);

    // 6. hid = gelu(ln2 @ W1 + b1) -> half
    gemm_h<EPI_GELU><<<dim3(HID / 128, MTOK / 128), 256>>>(p_l2h, p_W1t, b1, nullptr, p_hidh, MTOK, HID, DIM);

    // 7. out = xr + hid @ W2 + b2 (fp32)
    gemm_h<EPI_BIASRES><<<dim3(DIM / 128, MTOK / 128), 256>>>(p_hidh, p_W2t, b2, p_xr, out, MTOK, DIM, HID);
}

// round 6
// speedup vs baseline: 5.7611x; 1.3846x over previous
#include <cuda_runtime.h>
#include <cuda_fp16.h>
#include <cstdint>
#include <math.h>

// ---------------- problem constants ----------------
#define BATCH   16
#define HH      56
#define WW      56
#define DIM     384
#define HID     1536
#define WS      7
#define NWIN    1024
#define TSEQ    49
#define MTOK    50176
#define LN_EPS  1e-5f

// ---------------- device scratch ----------------
__device__ __align__(16) float  g_xB  [ (size_t)MTOK * DIM ];
__device__ __align__(16) float  g_xr  [ (size_t)MTOK * DIM ];
__device__ __align__(16) __half g_xwh [ (size_t)MTOK * DIM ];
__device__ __align__(16) __half g_hh  [ (size_t)MTOK * DIM ];
__device__ __align__(16) __half g_l2h [ (size_t)MTOK * DIM ];
__device__ __align__(16) __half g_hidh[ (size_t)MTOK * HID ];
__device__ __align__(16) __half g_Bmt [ DIM * DIM ];
__device__ __align__(16) __half g_Cmt [ DIM * DIM ];
__device__ __align__(16) __half g_At  [ DIM * DIM ];   // A^T [n][k] half
__device__ __align__(16) __half g_W1t [ (size_t)HID * DIM ];
__device__ __align__(16) __half g_W2t [ (size_t)DIM * HID ];

// ---------------- transpose + fp32->fp16 for weights ----------------
__global__ __launch_bounds__(256)
void transpose_h(const float* __restrict__ W, __half* __restrict__ Wt, int K, int N)
{
    __shared__ float tile[32][33];
    const int k0 = blockIdx.y * 32, n0 = blockIdx.x * 32;
    const int tx = threadIdx.x & 31, ty = threadIdx.x >> 5;
#pragma unroll
    for (int i = 0; i < 32; i += 8)
        tile[ty + i][tx] = W[(size_t)(k0 + ty + i) * N + n0 + tx];
    __syncthreads();
#pragma unroll
    for (int i = 0; i < 32; i += 8)
        Wt[(size_t)(n0 + ty + i) * K + k0 + tx] = __float2half_rn(tile[tx][ty + i]);
}

// ---------------- LayerNorm (warp per token) -> half, optional window remap ----------------
__global__ __launch_bounds__(256)
void ln_kernel(const float* __restrict__ x, const float* __restrict__ gw,
               const float* __restrict__ gb, __half* __restrict__ out, int remap)
{
    const int warp = threadIdx.x >> 5;
    const int lane = threadIdx.x & 31;
    const int token = blockIdx.x * 8 + warp;

    const float4* row = reinterpret_cast<const float4*>(x + (size_t)token * DIM);
    float4 v[3];
    float sum = 0.f, sq = 0.f;
#pragma unroll
    for (int q = 0; q < 3; q++) {
        v[q] = row[lane + 32 * q];
        sum += v[q].x + v[q].y + v[q].z + v[q].w;
        sq  += v[q].x * v[q].x + v[q].y * v[q].y + v[q].z * v[q].z + v[q].w * v[q].w;
    }
#pragma unroll
    for (int o = 16; o > 0; o >>= 1) {
        sum += __shfl_xor_sync(0xffffffffu, sum, o);
        sq  += __shfl_xor_sync(0xffffffffu, sq, o);
    }
    const float mu  = sum * (1.f / DIM);
    const float inv = rsqrtf(sq * (1.f / DIM) - mu * mu + LN_EPS);

    int orow = token;
    if (remap) {
        const int b   = token / (HH * WW);
        const int rem = token - b * (HH * WW);
        const int h   = rem / WW;
        const int w   = rem - h * WW;
        const int n   = b * 64 + (h / WS) * 8 + (w / WS);
        const int t   = (h % WS) * WS + (w % WS);
        orow = n * TSEQ + t;
    }
    __half* op = out + (size_t)orow * DIM;
    const float4* gw4 = reinterpret_cast<const float4*>(gw);
    const float4* gb4 = reinterpret_cast<const float4*>(gb);
#pragma unroll
    for (int q = 0; q < 3; q++) {
        const int c4 = lane + 32 * q;
        const float4 wv = gw4[c4];
        const float4 bv = gb4[c4];
        float rx = (v[q].x - mu) * inv * wv.x + bv.x;
        float ry = (v[q].y - mu) * inv * wv.y + bv.y;
        float rz = (v[q].z - mu) * inv * wv.z + bv.z;
        float rw = (v[q].w - mu) * inv * wv.w + bv.w;
        *reinterpret_cast<__half2*>(op + c4 * 4)     = __floats2half2_rn(rx, ry);
        *reinterpret_cast<__half2*>(op + c4 * 4 + 2) = __floats2half2_rn(rz, rw);
    }
}

// ---------------- MMA helpers ----------------
__device__ __forceinline__ void ldsm_x4(uint32_t& r0, uint32_t& r1, uint32_t& r2, uint32_t& r3, uint32_t addr)
{
    asm volatile("ldmatrix.sync.aligned.m8n8.x4.shared.b16 {%0,%1,%2,%3}, [%4];"
                 : "=r"(r0), "=r"(r1), "=r"(r2), "=r"(r3) : "r"(addr));
}
__device__ __forceinline__ void ldsm_x2(uint32_t& r0, uint32_t& r1, uint32_t addr)
{
    asm volatile("ldmatrix.sync.aligned.m8n8.x2.shared.b16 {%0,%1}, [%2];"
                 : "=r"(r0), "=r"(r1) : "r"(addr));
}
__device__ __forceinline__ void mma16816(float& c0, float& c1, float& c2, float& c3,
                                         uint32_t a0, uint32_t a1, uint32_t a2, uint32_t a3,
                                         uint32_t b0, uint32_t b1)
{
    asm volatile("mma.sync.aligned.m16n8k16.row.col.f32.f16.f16.f32 "
                 "{%0,%1,%2,%3}, {%4,%5,%6,%7}, {%8,%9}, {%0,%1,%2,%3};"
                 : "+f"(c0), "+f"(c1), "+f"(c2), "+f"(c3)
                 : "r"(a0), "r"(a1), "r"(a2), "r"(a3), "r"(b0), "r"(b1));
}
__device__ __forceinline__ void cp_async16(uint32_t dst, const void* src)
{
    asm volatile("cp.async.cg.shared.global [%0], [%1], 16;" :: "r"(dst), "l"(src));
}
__device__ __forceinline__ void cp_commit()
{
    asm volatile("cp.async.commit_group;");
}
template<int N> __device__ __forceinline__ void cp_wait()
{
    asm volatile("cp.async.wait_group %0;" :: "n"(N));
}

// ---------------- tensor-core scan: h_t = xB_t + h_{t-1} @ A ----------------
// 64 blocks x 16 windows. 8 warps, warp wn owns 48-col n-slice (6 mma n-tiles).
// h kept in smem (16 x 392 half). A^T streamed from L2 in 6 k-chunks of 64 via
// cp.async into a 3-stage ring (row pitch 72 halfs, conflict-free ldmatrix).
// Per chunk iteration: wait(chunk cur landed) -> barrier (all warps done with
// the buffer being overwritten) -> issue next chunk -> compute cur.
#define SPITCH 72
#define SBUFH  (DIM * SPITCH)       // 27648 halfs per A-chunk buffer
#define HPITCH 392
#define SCAN_SMEM ((3 * SBUFH + 16 * HPITCH) * 2)

__global__ __launch_bounds__(256)
void scan_mma(const float* __restrict__ xB, const __half* __restrict__ At,
              __half* __restrict__ hout)
{
    extern __shared__ __half smem[];
    __half* sH = smem + 3 * SBUFH;

    const int tid  = threadIdx.x;
    const int lane = tid & 31;
    const int wn   = tid >> 5;                 // 0..7, n-slice base wn*48
    const int gr   = lane >> 2, tg = lane & 3;
    const int n0   = blockIdx.x * 16;

    const uint32_t sAbase = (uint32_t)__cvta_generic_to_shared(smem);
    const uint32_t sHbase = (uint32_t)__cvta_generic_to_shared(sH);

    // ldmatrix lane addresses
    const uint32_t hOff = (uint32_t)(((((lane >> 3) & 1) * 8 + (lane & 7)) * HPITCH + (lane >> 4) * 8) * 2);
    const uint32_t bOff = (uint32_t)(((wn * 48 + (lane & 7)) * SPITCH + ((lane >> 3) & 1) * 8) * 2);

    // per-thread output columns / windows
    const int colb = wn * 48 + tg * 2;             // + ni*8
    const int w0 = n0 + gr, w1 = n0 + gr + 8;
    const float* xB0 = xB + (size_t)w0 * TSEQ * DIM;
    const float* xB1 = xB + (size_t)w1 * TSEQ * DIM;
    __half* ho0 = hout + (size_t)w0 * TSEQ * DIM;
    __half* ho1 = hout + (size_t)w1 * TSEQ * DIM;

    // ---- chunk issue helper (chunk c of A^T -> ring buffer b) ----
    auto issue = [&](int c, int b) {
        const uint32_t dbase = sAbase + (uint32_t)b * (SBUFH * 2);
#pragma unroll
        for (int i = 0; i < 12; i++) {
            const int idx = i * 256 + tid;       // 0..3071
            const int row = idx >> 3, seg = idx & 7;
            cp_async16(dbase + (uint32_t)(row * SPITCH + seg * 8) * 2,
                       At + (size_t)row * DIM + c * 64 + seg * 8);
        }
        cp_commit();
    };

    issue(0, 0);
    issue(1, 1);
    int nxt = 2;

    float acc[6][4];

    // ---- t = 0: h = xB ----
#pragma unroll
    for (int ni = 0; ni < 6; ni++) {
        const float2 a = *reinterpret_cast<const float2*>(xB0 + colb + ni * 8);
        const float2 b = *reinterpret_cast<const float2*>(xB1 + colb + ni * 8);
        acc[ni][0] = a.x; acc[ni][1] = a.y; acc[ni][2] = b.x; acc[ni][3] = b.y;
        const __half2 h0 = __floats2half2_rn(a.x, a.y);
        const __half2 h1 = __floats2half2_rn(b.x, b.y);
        *reinterpret_cast<__half2*>(&sH[gr * HPITCH + colb + ni * 8])       = h0;
        *reinterpret_cast<__half2*>(&sH[(gr + 8) * HPITCH + colb + ni * 8]) = h1;
        *reinterpret_cast<__half2*>(ho0 + colb + ni * 8) = h0;
        *reinterpret_cast<__half2*>(ho1 + colb + ni * 8) = h1;
    }

    for (int t = 1; t < TSEQ; t++) {
#pragma unroll
        for (int ni = 0; ni < 6; ni++) {
            const float2 a = *reinterpret_cast<const float2*>(xB0 + (size_t)t * DIM + colb + ni * 8);
            const float2 b = *reinterpret_cast<const float2*>(xB1 + (size_t)t * DIM + colb + ni * 8);
            acc[ni][0] = a.x; acc[ni][1] = a.y; acc[ni][2] = b.x; acc[ni][3] = b.y;
        }

        for (int cc = 0; cc < 6; cc++) {
            const int cur = nxt - 2;          // chunk to compute this iteration
            cp_wait<1>();                     // chunk cur has landed
            __syncthreads();                  // visible to all; buffer nxt%3 free to overwrite
            issue(nxt % 6, nxt % 3);
            nxt++;
            const uint32_t bufB = sAbase + (uint32_t)(cur % 3) * (SBUFH * 2) + bOff;
#pragma unroll
            for (int kt = 0; kt < 4; kt++) {
                uint32_t a0, a1, a2, a3;
                ldsm_x4(a0, a1, a2, a3, sHbase + hOff + (uint32_t)(cc * 4 + kt) * 32);
#pragma unroll
                for (int ni = 0; ni < 6; ni++) {
                    uint32_t b0, b1;
                    ldsm_x2(b0, b1, bufB + (uint32_t)(ni * 8 * SPITCH * 2) + (uint32_t)kt * 32);
                    mma16816(acc[ni][0], acc[ni][1], acc[ni][2], acc[ni][3],
                             a0, a1, a2, a3, b0, b1);
                }
            }
        }
        __syncthreads();                      // all warps done reading h_{t-1}
#pragma unroll
        for (int ni = 0; ni < 6; ni++) {
            const __half2 h0 = __floats2half2_rn(acc[ni][0], acc[ni][1]);
            const __half2 h1 = __floats2half2_rn(acc[ni][2], acc[ni][3]);
            if (t + 1 < TSEQ) {
                *reinterpret_cast<__half2*>(&sH[gr * HPITCH + colb + ni * 8])       = h0;
                *reinterpret_cast<__half2*>(&sH[(gr + 8) * HPITCH + colb + ni * 8]) = h1;
            }
            *reinterpret_cast<__half2*>(ho0 + (size_t)t * DIM + colb + ni * 8) = h0;
            *reinterpret_cast<__half2*>(ho1 + (size_t)t * DIM + colb + ni * 8) = h1;
        }
    }
    cp_wait<0>();
}

// ---------------- fp16 tensor-core GEMM: C[M,N] = A[M,K] @ Bt[N,K]^T ----------------
#define EPI_NONE    0
#define EPI_WINREV  1
#define EPI_GELU    2
#define EPI_BIASRES 3

#define PADH  40
#define ASTRH (128 * PADH)

__device__ __forceinline__ float gelu_exact(float v)
{
    return 0.5f * v * (1.f + erff(v * 0.70710678118654752f));
}

template<int EPI>
__global__ __launch_bounds__(256)
void gemm_h(const __half* __restrict__ Ag, const __half* __restrict__ Bg,
            const float* __restrict__ bias, const float* __restrict__ res,
            void* __restrict__ Cv, int M, int N, int K)
{
    __shared__ __align__(16) __half As[2][ASTRH];
    __shared__ __align__(16) __half Bs[2][ASTRH];

    const int tid  = threadIdx.x;
    const int lane = tid & 31;
    const int wid  = tid >> 5;
    const int wm   = wid >> 1;
    const int wn   = wid & 1;
    const int m0   = blockIdx.y * 128;
    const int n0   = blockIdx.x * 128;

    const int c0r = tid >> 2,         c0o = (tid & 3) * 8;
    const int c1r = (tid + 256) >> 2, c1o = ((tid + 256) & 3) * 8;
    const __half* Ap0 = Ag + (size_t)(m0 + c0r) * K + c0o;
    const __half* Ap1 = Ag + (size_t)(m0 + c1r) * K + c1o;
    const __half* Bp0 = Bg + (size_t)(n0 + c0r) * K + c0o;
    const __half* Bp1 = Bg + (size_t)(n0 + c1r) * K + c1o;
    const int sa0 = c0r * PADH + c0o;
    const int sa1 = c1r * PADH + c1o;

    const uint32_t asB = (uint32_t)__cvta_generic_to_shared(&As[0][0]);
    const uint32_t bsB = (uint32_t)__cvta_generic_to_shared(&Bs[0][0]);

    const int l7 = lane & 7;
    const uint32_t aOff = (uint32_t)(((wm * 32 + ((lane >> 3) & 1) * 8 + l7) * PADH + (lane >> 4) * 8) * 2);
    const int bl = lane & 15;
    const uint32_t bOff = (uint32_t)(((wn * 64 + (bl & 7)) * PADH + (bl >> 3) * 8) * 2);

    float acc[2][8][4];
#pragma unroll
    for (int mi = 0; mi < 2; mi++)
#pragma unroll
        for (int ni = 0; ni < 8; ni++)
#pragma unroll
            for (int q = 0; q < 4; q++) acc[mi][ni][q] = 0.f;

    int4 pa0 = *reinterpret_cast<const int4*>(Ap0);
    int4 pa1 = *reinterpret_cast<const int4*>(Ap1);
    int4 pb0 = *reinterpret_cast<const int4*>(Bp0);
    int4 pb1 = *reinterpret_cast<const int4*>(Bp1);
    *reinterpret_cast<int4*>(&As[0][sa0]) = pa0;
    *reinterpret_cast<int4*>(&As[0][sa1]) = pa1;
    *reinterpret_cast<int4*>(&Bs[0][sa0]) = pb0;
    *reinterpret_cast<int4*>(&Bs[0][sa1]) = pb1;
    __syncthreads();

    const int nk = K >> 5;
    for (int kt = 0; kt < nk; kt++) {
        const int buf = kt & 1;
        if (kt + 1 < nk) {
            pa0 = *reinterpret_cast<const int4*>(Ap0 + (kt + 1) * 32);
            pa1 = *reinterpret_cast<const int4*>(Ap1 + (kt + 1) * 32);
            pb0 = *reinterpret_cast<const int4*>(Bp0 + (kt + 1) * 32);
            pb1 = *reinterpret_cast<const int4*>(Bp1 + (kt + 1) * 32);
        }
        const uint32_t aB = asB + buf * (ASTRH * 2) + aOff;
        const uint32_t bB = bsB + buf * (ASTRH * 2) + bOff;
#pragma unroll
        for (int kk = 0; kk < 2; kk++) {
            uint32_t a[2][4], bf[8][2];
            ldsm_x4(a[0][0], a[0][1], a[0][2], a[0][3], aB + kk * 32);
            ldsm_x4(a[1][0], a[1][1], a[1][2], a[1][3], aB + kk * 32 + 16 * PADH * 2);
#pragma unroll
            for (int ni = 0; ni < 8; ni++)
                ldsm_x2(bf[ni][0], bf[ni][1], bB + kk * 32 + ni * 8 * PADH * 2);
#pragma unroll
            for (int mi = 0; mi < 2; mi++)
#pragma unroll
                for (int ni = 0; ni < 8; ni++)
                    mma16816(acc[mi][ni][0], acc[mi][ni][1], acc[mi][ni][2], acc[mi][ni][3],
                             a[mi][0], a[mi][1], a[mi][2], a[mi][3], bf[ni][0], bf[ni][1]);
        }
        if (kt + 1 < nk) {
            const int nb = buf ^ 1;
            *reinterpret_cast<int4*>(&As[nb][sa0]) = pa0;
            *reinterpret_cast<int4*>(&As[nb][sa1]) = pa1;
            *reinterpret_cast<int4*>(&Bs[nb][sa0]) = pb0;
            *reinterpret_cast<int4*>(&Bs[nb][sa1]) = pb1;
        }
        __syncthreads();
    }

    const int gr = lane >> 2, tg = lane & 3;

    float2 bias2[8];
    if (EPI == EPI_GELU || EPI == EPI_BIASRES) {
#pragma unroll
        for (int ni = 0; ni < 8; ni++)
            bias2[ni] = *reinterpret_cast<const float2*>(bias + n0 + wn * 64 + ni * 8 + tg * 2);
    }

#pragma unroll
    for (int mi = 0; mi < 2; mi++)
#pragma unroll
    for (int rh = 0; rh < 2; rh++) {
        const int gm = m0 + wm * 32 + mi * 16 + rh * 8 + gr;
        int orow = gm;
        if (EPI == EPI_WINREV) {
            const int n = gm / TSEQ;
            const int t = gm - n * TSEQ;
            const int b = n >> 6;
            const int rm = n & 63;
            const int wh = rm >> 3, wwi = rm & 7;
            const int ti = t / WS, tj = t - ti * WS;
            orow = (b * HH + wh * WS + ti) * WW + wwi * WS + tj;
        }
#pragma unroll
        for (int ni = 0; ni < 8; ni++) {
            const int col = n0 + wn * 64 + ni * 8 + tg * 2;
            float v0 = acc[mi][ni][rh * 2];
            float v1 = acc[mi][ni][rh * 2 + 1];
            if (EPI == EPI_GELU) {
                v0 = gelu_exact(v0 + bias2[ni].x);
                v1 = gelu_exact(v1 + bias2[ni].y);
                __half* C = (__half*)Cv;
                *reinterpret_cast<__half2*>(C + (size_t)orow * N + col) = __floats2half2_rn(v0, v1);
            } else {
                if (EPI == EPI_BIASRES) {
                    const float2 r = *reinterpret_cast<const float2*>(res + (size_t)gm * N + col);
                    v0 += bias2[ni].x + r.x;
                    v1 += bias2[ni].y + r.y;
                }
                float* C = (float*)Cv;
                float2 o; o.x = v0; o.y = v1;
                *reinterpret_cast<float2*>(C + (size_t)orow * N + col) = o;
            }
        }
    }
}

// ---------------- launch ----------------
extern "C" void kernel_launch(void* const* d_in, const int* in_sizes, int n_in,
                              void* d_out, int out_size)
{
    const float* x    = (const float*)d_in[0];
    const float* A    = (const float*)d_in[1];
    const float* Bm   = (const float*)d_in[2];
    const float* Cm   = (const float*)d_in[3];
    const float* ln1w = (const float*)d_in[4];
    const float* ln1b = (const float*)d_in[5];
    const float* ln2w = (const float*)d_in[6];
    const float* ln2b = (const float*)d_in[7];
    const float* W1   = (const float*)d_in[8];
    const float* b1   = (const float*)d_in[9];
    const float* W2   = (const float*)d_in[10];
    const float* b2   = (const float*)d_in[11];
    float* out = (float*)d_out;

    float  *p_xB, *p_xr;
    __half *p_xwh, *p_hh, *p_l2h, *p_hidh, *p_Bmt, *p_Cmt, *p_At, *p_W1t, *p_W2t;
    cudaGetSymbolAddress((void**)&p_xB,   g_xB);
    cudaGetSymbolAddress((void**)&p_xr,   g_xr);
    cudaGetSymbolAddress((void**)&p_xwh,  g_xwh);
    cudaGetSymbolAddress((void**)&p_hh,   g_hh);
    cudaGetSymbolAddress((void**)&p_l2h,  g_l2h);
    cudaGetSymbolAddress((void**)&p_hidh, g_hidh);
    cudaGetSymbolAddress((void**)&p_Bmt,  g_Bmt);
    cudaGetSymbolAddress((void**)&p_Cmt,  g_Cmt);
    cudaGetSymbolAddress((void**)&p_At,   g_At);
    cudaGetSymbolAddress((void**)&p_W1t,  g_W1t);
    cudaGetSymbolAddress((void**)&p_W2t,  g_W2t);

    cudaFuncSetAttribute(scan_mma, cudaFuncAttributeMaxDynamicSharedMemorySize, SCAN_SMEM);

    // 0. weight transposes -> half [N][K]
    transpose_h<<<dim3(DIM / 32, DIM / 32), 256>>>(Bm, p_Bmt, DIM, DIM);
    transpose_h<<<dim3(DIM / 32, DIM / 32), 256>>>(Cm, p_Cmt, DIM, DIM);
    transpose_h<<<dim3(DIM / 32, DIM / 32), 256>>>(A,  p_At,  DIM, DIM);
    transpose_h<<<dim3(HID / 32, DIM / 32), 256>>>(W1, p_W1t, DIM, HID);
    transpose_h<<<dim3(DIM / 32, HID / 32), 256>>>(W2, p_W2t, HID, DIM);

    // 1. LN1 + window partition -> half
    ln_kernel<<<MTOK / 8, 256>>>(x, ln1w, ln1b, p_xwh, 1);

    // 2. xB = xw @ Bm  (fp32 out, scan input)
    gemm_h<EPI_NONE><<<dim3(DIM / 128, MTOK / 128), 256>>>(p_xwh, p_Bmt, nullptr, nullptr, p_xB, MTOK, DIM, DIM);

    // 3. tensor-core sequential scan -> half states
    scan_mma<<<NWIN / 16, 256, SCAN_SMEM>>>(p_xB, p_At, p_hh);

    // 4. xr = h @ Cm, fused window-reverse (fp32 out)
    gemm_h<EPI_WINREV><<<dim3(DIM / 128, MTOK / 128), 256>>>(p_hh, p_Cmt, nullptr, nullptr, p_xr, MTOK, DIM, DIM);

    // 5. LN2 -> half
    ln_kernel<<<MTOK / 8, 256>>>(p_xr, ln2w, ln2b, p_l2h, 0);

    // 6. hid = gelu(ln2 @ W1 + b1) -> half
    gemm_h<EPI_GELU><<<dim3(HID / 128, MTOK / 128), 256>>>(p_l2h, p_W1t, b1, nullptr, p_hidh, MTOK, HID, DIM);

    // 7. out = xr + hid @ W2 + b2 (fp32)
    gemm_h<EPI_BIASRES><<<dim3(DIM / 128, MTOK / 128), 256>>>(p_hidh, p_W2t, b2, p_xr, out, MTOK, DIM, HID);
}

// round 12
// speedup vs baseline: 6.0324x; 1.0471x over previous
#include <cuda_runtime.h>
#include <cuda_fp16.h>
#include <cstdint>
#include <math.h>

// ---------------- problem constants ----------------
#define BATCH   16
#define HH      56
#define WW      56
#define DIM     384
#define HID     1536
#define WS      7
#define NWIN    1024
#define TSEQ    49
#define MTOK    50176
#define LN_EPS  1e-5f

// ---------------- device scratch ----------------
__device__ __align__(16) float  g_xB  [ (size_t)MTOK * DIM ];
__device__ __align__(16) float  g_xr  [ (size_t)MTOK * DIM ];
__device__ __align__(16) __half g_xwh [ (size_t)MTOK * DIM ];
__device__ __align__(16) __half g_hh  [ (size_t)MTOK * DIM ];
__device__ __align__(16) __half g_l2h [ (size_t)MTOK * DIM ];
__device__ __align__(16) __half g_hidh[ (size_t)MTOK * HID ];
__device__ __align__(16) __half g_Bmt [ DIM * DIM ];
__device__ __align__(16) __half g_Cmt [ DIM * DIM ];
__device__ __align__(16) __half g_At  [ DIM * DIM ];   // A^T [n][k] half
__device__ __align__(16) __half g_W1t [ (size_t)HID * DIM ];
__device__ __align__(16) __half g_W2t [ (size_t)DIM * HID ];

// ---------------- transpose + fp32->fp16 for weights ----------------
__global__ __launch_bounds__(256)
void transpose_h(const float* __restrict__ W, __half* __restrict__ Wt, int K, int N)
{
    __shared__ float tile[32][33];
    const int k0 = blockIdx.y * 32, n0 = blockIdx.x * 32;
    const int tx = threadIdx.x & 31, ty = threadIdx.x >> 5;
#pragma unroll
    for (int i = 0; i < 32; i += 8)
        tile[ty + i][tx] = W[(size_t)(k0 + ty + i) * N + n0 + tx];
    __syncthreads();
#pragma unroll
    for (int i = 0; i < 32; i += 8)
        Wt[(size_t)(n0 + ty + i) * K + k0 + tx] = __float2half_rn(tile[tx][ty + i]);
}

// ---------------- LayerNorm (warp per token) -> half, optional window remap ----------------
__global__ __launch_bounds__(256)
void ln_kernel(const float* __restrict__ x, const float* __restrict__ gw,
               const float* __restrict__ gb, __half* __restrict__ out, int remap)
{
    const int warp = threadIdx.x >> 5;
    const int lane = threadIdx.x & 31;
    const int token = blockIdx.x * 8 + warp;

    const float4* row = reinterpret_cast<const float4*>(x + (size_t)token * DIM);
    float4 v[3];
    float sum = 0.f, sq = 0.f;
#pragma unroll
    for (int q = 0; q < 3; q++) {
        v[q] = row[lane + 32 * q];
        sum += v[q].x + v[q].y + v[q].z + v[q].w;
        sq  += v[q].x * v[q].x + v[q].y * v[q].y + v[q].z * v[q].z + v[q].w * v[q].w;
    }
#pragma unroll
    for (int o = 16; o > 0; o >>= 1) {
        sum += __shfl_xor_sync(0xffffffffu, sum, o);
        sq  += __shfl_xor_sync(0xffffffffu, sq, o);
    }
    const float mu  = sum * (1.f / DIM);
    const float inv = rsqrtf(sq * (1.f / DIM) - mu * mu + LN_EPS);

    int orow = token;
    if (remap) {
        const int b   = token / (HH * WW);
        const int rem = token - b * (HH * WW);
        const int h   = rem / WW;
        const int w   = rem - h * WW;
        const int n   = b * 64 + (h / WS) * 8 + (w / WS);
        const int t   = (h % WS) * WS + (w % WS);
        orow = n * TSEQ + t;
    }
    __half* op = out + (size_t)orow * DIM;
    const float4* gw4 = reinterpret_cast<const float4*>(gw);
    const float4* gb4 = reinterpret_cast<const float4*>(gb);
#pragma unroll
    for (int q = 0; q < 3; q++) {
        const int c4 = lane + 32 * q;
        const float4 wv = gw4[c4];
        const float4 bv = gb4[c4];
        float rx = (v[q].x - mu) * inv * wv.x + bv.x;
        float ry = (v[q].y - mu) * inv * wv.y + bv.y;
        float rz = (v[q].z - mu) * inv * wv.z + bv.z;
        float rw = (v[q].w - mu) * inv * wv.w + bv.w;
        *reinterpret_cast<__half2*>(op + c4 * 4)     = __floats2half2_rn(rx, ry);
        *reinterpret_cast<__half2*>(op + c4 * 4 + 2) = __floats2half2_rn(rz, rw);
    }
}

// ---------------- MMA helpers ----------------
__device__ __forceinline__ void ldsm_x4(uint32_t& r0, uint32_t& r1, uint32_t& r2, uint32_t& r3, uint32_t addr)
{
    asm volatile("ldmatrix.sync.aligned.m8n8.x4.shared.b16 {%0,%1,%2,%3}, [%4];"
                 : "=r"(r0), "=r"(r1), "=r"(r2), "=r"(r3) : "r"(addr));
}
__device__ __forceinline__ void ldsm_x2(uint32_t& r0, uint32_t& r1, uint32_t addr)
{
    asm volatile("ldmatrix.sync.aligned.m8n8.x2.shared.b16 {%0,%1}, [%2];"
                 : "=r"(r0), "=r"(r1) : "r"(addr));
}
__device__ __forceinline__ void mma16816(float& c0, float& c1, float& c2, float& c3,
                                         uint32_t a0, uint32_t a1, uint32_t a2, uint32_t a3,
                                         uint32_t b0, uint32_t b1)
{
    asm volatile("mma.sync.aligned.m16n8k16.row.col.f32.f16.f16.f32 "
                 "{%0,%1,%2,%3}, {%4,%5,%6,%7}, {%8,%9}, {%0,%1,%2,%3};"
                 : "+f"(c0), "+f"(c1), "+f"(c2), "+f"(c3)
                 : "r"(a0), "r"(a1), "r"(a2), "r"(a3), "r"(b0), "r"(b1));
}
__device__ __forceinline__ void cp_async16(uint32_t dst, const void* src)
{
    asm volatile("cp.async.cg.shared.global [%0], [%1], 16;" :: "r"(dst), "l"(src));
}
__device__ __forceinline__ void cp_commit()
{
    asm volatile("cp.async.commit_group;");
}
template<int N> __device__ __forceinline__ void cp_wait()
{
    asm volatile("cp.async.wait_group %0;" :: "n"(N));
}

// ---------------- tensor-core scan: h_t = xB_t + h_{t-1} @ A ----------------
#define SPITCH 72
#define SBUFH  (DIM * SPITCH)
#define HPITCH 392
#define SCAN_SMEM ((3 * SBUFH + 16 * HPITCH) * 2)

__global__ __launch_bounds__(256)
void scan_mma(const float* __restrict__ xB, const __half* __restrict__ At,
              __half* __restrict__ hout)
{
    extern __shared__ __half smem[];
    __half* sH = smem + 3 * SBUFH;

    const int tid  = threadIdx.x;
    const int lane = tid & 31;
    const int wn   = tid >> 5;
    const int gr   = lane >> 2, tg = lane & 3;
    const int n0   = blockIdx.x * 16;

    const uint32_t sAbase = (uint32_t)__cvta_generic_to_shared(smem);
    const uint32_t sHbase = (uint32_t)__cvta_generic_to_shared(sH);

    const uint32_t hOff = (uint32_t)(((((lane >> 3) & 1) * 8 + (lane & 7)) * HPITCH + (lane >> 4) * 8) * 2);
    const uint32_t bOff = (uint32_t)(((wn * 48 + (lane & 7)) * SPITCH + ((lane >> 3) & 1) * 8) * 2);

    const int colb = wn * 48 + tg * 2;
    const int w0 = n0 + gr, w1 = n0 + gr + 8;
    const float* xB0 = xB + (size_t)w0 * TSEQ * DIM;
    const float* xB1 = xB + (size_t)w1 * TSEQ * DIM;
    __half* ho0 = hout + (size_t)w0 * TSEQ * DIM;
    __half* ho1 = hout + (size_t)w1 * TSEQ * DIM;

    auto issue = [&](int c, int b) {
        const uint32_t dbase = sAbase + (uint32_t)b * (SBUFH * 2);
#pragma unroll
        for (int i = 0; i < 12; i++) {
            const int idx = i * 256 + tid;
            const int row = idx >> 3, seg = idx & 7;
            cp_async16(dbase + (uint32_t)(row * SPITCH + seg * 8) * 2,
                       At + (size_t)row * DIM + c * 64 + seg * 8);
        }
        cp_commit();
    };

    issue(0, 0);
    issue(1, 1);
    int nxt = 2;

    float acc[6][4];

#pragma unroll
    for (int ni = 0; ni < 6; ni++) {
        const float2 a = *reinterpret_cast<const float2*>(xB0 + colb + ni * 8);
        const float2 b = *reinterpret_cast<const float2*>(xB1 + colb + ni * 8);
        acc[ni][0] = a.x; acc[ni][1] = a.y; acc[ni][2] = b.x; acc[ni][3] = b.y;
        const __half2 h0 = __floats2half2_rn(a.x, a.y);
        const __half2 h1 = __floats2half2_rn(b.x, b.y);
        *reinterpret_cast<__half2*>(&sH[gr * HPITCH + colb + ni * 8])       = h0;
        *reinterpret_cast<__half2*>(&sH[(gr + 8) * HPITCH + colb + ni * 8]) = h1;
        *reinterpret_cast<__half2*>(ho0 + colb + ni * 8) = h0;
        *reinterpret_cast<__half2*>(ho1 + colb + ni * 8) = h1;
    }

    for (int t = 1; t < TSEQ; t++) {
#pragma unroll
        for (int ni = 0; ni < 6; ni++) {
            const float2 a = *reinterpret_cast<const float2*>(xB0 + (size_t)t * DIM + colb + ni * 8);
            const float2 b = *reinterpret_cast<const float2*>(xB1 + (size_t)t * DIM + colb + ni * 8);
            acc[ni][0] = a.x; acc[ni][1] = a.y; acc[ni][2] = b.x; acc[ni][3] = b.y;
        }

        for (int cc = 0; cc < 6; cc++) {
            const int cur = nxt - 2;
            cp_wait<1>();
            __syncthreads();
            issue(nxt % 6, nxt % 3);
            nxt++;
            const uint32_t bufB = sAbase + (uint32_t)(cur % 3) * (SBUFH * 2) + bOff;
#pragma unroll
            for (int kt = 0; kt < 4; kt++) {
                uint32_t a0, a1, a2, a3;
                ldsm_x4(a0, a1, a2, a3, sHbase + hOff + (uint32_t)(cc * 4 + kt) * 32);
#pragma unroll
                for (int ni = 0; ni < 6; ni++) {
                    uint32_t b0, b1;
                    ldsm_x2(b0, b1, bufB + (uint32_t)(ni * 8 * SPITCH * 2) + (uint32_t)kt * 32);
                    mma16816(acc[ni][0], acc[ni][1], acc[ni][2], acc[ni][3],
                             a0, a1, a2, a3, b0, b1);
                }
            }
        }
        __syncthreads();
#pragma unroll
        for (int ni = 0; ni < 6; ni++) {
            const __half2 h0 = __floats2half2_rn(acc[ni][0], acc[ni][1]);
            const __half2 h1 = __floats2half2_rn(acc[ni][2], acc[ni][3]);
            if (t + 1 < TSEQ) {
                *reinterpret_cast<__half2*>(&sH[gr * HPITCH + colb + ni * 8])       = h0;
                *reinterpret_cast<__half2*>(&sH[(gr + 8) * HPITCH + colb + ni * 8]) = h1;
            }
            *reinterpret_cast<__half2*>(ho0 + (size_t)t * DIM + colb + ni * 8) = h0;
            *reinterpret_cast<__half2*>(ho1 + (size_t)t * DIM + colb + ni * 8) = h1;
        }
    }
    cp_wait<0>();
}

// ---------------- fp16 tensor-core GEMM, cp.async 3-stage pipeline ----------------
// C[M,N] = A[M,K] @ Bt[N,K]^T.  128x128 CTA tile, BK=32, 8 warps 4x2.
#define EPI_NONE    0
#define EPI_WINREV  1
#define EPI_GELU    2
#define EPI_BIASRES 3

#define PADH   40                 // halfs per smem row
#define STGH   (128 * PADH)       // halfs per operand per stage
#define GEMM_SMEM (3 * 2 * STGH * 2)   // 3 stages x (A+B) x bytes = 61440

__device__ __forceinline__ float gelu_exact(float v)
{
    return 0.5f * v * (1.f + erff(v * 0.70710678118654752f));
}

template<int EPI>
__global__ __launch_bounds__(256)
void gemm_h(const __half* __restrict__ Ag, const __half* __restrict__ Bg,
            const float* __restrict__ bias, const float* __restrict__ res,
            void* __restrict__ Cv, int M, int N, int K)
{
    extern __shared__ __align__(16) __half gsm[];

    const int tid  = threadIdx.x;
    const int lane = tid & 31;
    const int wid  = tid >> 5;
    const int wm   = wid >> 1;          // 0..3
    const int wn   = wid & 1;           // 0..1
    const int m0   = blockIdx.y * 128;
    const int n0   = blockIdx.x * 128;

    const uint32_t smB = (uint32_t)__cvta_generic_to_shared(gsm);

    // cp.async staging: per stage, per operand: 128 rows x 32 halfs = 512 x 16B.
    // thread t covers chunks t and t+256 of each operand.
    const int c0r = tid >> 1,  c0s = (tid & 1) * 2;        // rows 0..127, seg 0/2
    // chunk mapping: chunk c: row=c>>2, seg=c&3. t -> c=t: row=t>>2,seg=t&3. Use two:
    const int r0 = tid >> 2, s0 = tid & 3;
    const int r1 = (tid + 256) >> 2, s1 = (tid + 256) & 3;
    (void)c0r; (void)c0s;

    const __half* ApG = Ag + (size_t)(m0 + r0) * K + s0 * 8;
    const __half* ApG1 = Ag + (size_t)(m0 + r1) * K + s1 * 8;
    const __half* BpG = Bg + (size_t)(n0 + r0) * K + s0 * 8;
    const __half* BpG1 = Bg + (size_t)(n0 + r1) * K + s1 * 8;
    const uint32_t sa0 = (uint32_t)(r0 * PADH + s0 * 8) * 2;
    const uint32_t sa1 = (uint32_t)(r1 * PADH + s1 * 8) * 2;

    auto load_stage = [&](int kt, int stg) {
        const uint32_t base = smB + (uint32_t)stg * (2 * STGH * 2);
        const size_t ko = (size_t)kt * 32;
        cp_async16(base + sa0,                ApG  + ko);
        cp_async16(base + sa1,                ApG1 + ko);
        cp_async16(base + STGH * 2 + sa0,     BpG  + ko);
        cp_async16(base + STGH * 2 + sa1,     BpG1 + ko);
        cp_commit();
    };

    // ldmatrix lane addresses (byte offsets within a stage)
    const uint32_t aOff = (uint32_t)(((wm * 32 + ((lane >> 3) & 1) * 8 + (lane & 7)) * PADH + (lane >> 4) * 8) * 2);
    // B x4: lanes 0-15 n-rows +0..7 (cols 0/8), lanes 16-31 n-rows +8..15
    const uint32_t bOff = (uint32_t)(((wn * 64 + ((lane >> 4) & 1) * 8 + (lane & 7)) * PADH + ((lane >> 3) & 1) * 8) * 2);

    float acc[2][8][4];
#pragma unroll
    for (int mi = 0; mi < 2; mi++)
#pragma unroll
        for (int ni = 0; ni < 8; ni++)
#pragma unroll
            for (int q = 0; q < 4; q++) acc[mi][ni][q] = 0.f;

    const int NK = K >> 5;
    load_stage(0, 0);
    load_stage(1, 1);

    for (int kt = 0; kt < NK; kt++) {
        if (kt + 1 < NK) cp_wait<1>(); else cp_wait<0>();
        __syncthreads();
        if (kt + 2 < NK) load_stage(kt + 2, (kt + 2) % 3);

        const uint32_t stgB = smB + (uint32_t)(kt % 3) * (2 * STGH * 2);
        const uint32_t aB = stgB + aOff;
        const uint32_t bB = stgB + STGH * 2 + bOff;
#pragma unroll
        for (int kk = 0; kk < 2; kk++) {
            uint32_t a[2][4], bf[8][2];
            ldsm_x4(a[0][0], a[0][1], a[0][2], a[0][3], aB + kk * 32);
            ldsm_x4(a[1][0], a[1][1], a[1][2], a[1][3], aB + kk * 32 + 16 * PADH * 2);
#pragma unroll
            for (int nj = 0; nj < 4; nj++)
                ldsm_x4(bf[nj * 2][0], bf[nj * 2][1], bf[nj * 2 + 1][0], bf[nj * 2 + 1][1],
                        bB + kk * 32 + (uint32_t)(nj * 16 * PADH * 2));
#pragma unroll
            for (int mi = 0; mi < 2; mi++)
#pragma unroll
                for (int ni = 0; ni < 8; ni++)
                    mma16816(acc[mi][ni][0], acc[mi][ni][1], acc[mi][ni][2], acc[mi][ni][3],
                             a[mi][0], a[mi][1], a[mi][2], a[mi][3], bf[ni][0], bf[ni][1]);
        }
    }

    // ---------------- epilogue ----------------
    const int gr = lane >> 2, tg = lane & 3;

    float2 bias2[8];
    if (EPI == EPI_GELU || EPI == EPI_BIASRES) {
#pragma unroll
        for (int ni = 0; ni < 8; ni++)
            bias2[ni] = *reinterpret_cast<const float2*>(bias + n0 + wn * 64 + ni * 8 + tg * 2);
    }

#pragma unroll
    for (int mi = 0; mi < 2; mi++)
#pragma unroll
    for (int rh = 0; rh < 2; rh++) {
        const int gm = m0 + wm * 32 + mi * 16 + rh * 8 + gr;
        int orow = gm;
        if (EPI == EPI_WINREV) {
            const int n = gm / TSEQ;
            const int t = gm - n * TSEQ;
            const int b = n >> 6;
            const int rm = n & 63;
            const int wh = rm >> 3, wwi = rm & 7;
            const int ti = t / WS, tj = t - ti * WS;
            orow = (b * HH + wh * WS + ti) * WW + wwi * WS + tj;
        }
#pragma unroll
        for (int ni = 0; ni < 8; ni++) {
            const int col = n0 + wn * 64 + ni * 8 + tg * 2;
            float v0 = acc[mi][ni][rh * 2];
            float v1 = acc[mi][ni][rh * 2 + 1];
            if (EPI == EPI_GELU) {
                v0 = gelu_exact(v0 + bias2[ni].x);
                v1 = gelu_exact(v1 + bias2[ni].y);
                __half* C = (__half*)Cv;
                *reinterpret_cast<__half2*>(C + (size_t)orow * N + col) = __floats2half2_rn(v0, v1);
            } else {
                if (EPI == EPI_BIASRES) {
                    const float2 r = *reinterpret_cast<const float2*>(res + (size_t)gm * N + col);
                    v0 += bias2[ni].x + r.x;
                    v1 += bias2[ni].y + r.y;
                }
                float* C = (float*)Cv;
                float2 o; o.x = v0; o.y = v1;
                *reinterpret_cast<float2*>(C + (size_t)orow * N + col) = o;
            }
        }
    }
}

// ---------------- launch ----------------
extern "C" void kernel_launch(void* const* d_in, const int* in_sizes, int n_in,
                              void* d_out, int out_size)
{
    const float* x    = (const float*)d_in[0];
    const float* A    = (const float*)d_in[1];
    const float* Bm   = (const float*)d_in[2];
    const float* Cm   = (const float*)d_in[3];
    const float* ln1w = (const float*)d_in[4];
    const float* ln1b = (const float*)d_in[5];
    const float* ln2w = (const float*)d_in[6];
    const float* ln2b = (const float*)d_in[7];
    const float* W1   = (const float*)d_in[8];
    const float* b1   = (const float*)d_in[9];
    const float* W2   = (const float*)d_in[10];
    const float* b2   = (const float*)d_in[11];
    float* out = (float*)d_out;

    float  *p_xB, *p_xr;
    __half *p_xwh, *p_hh, *p_l2h, *p_hidh, *p_Bmt, *p_Cmt, *p_At, *p_W1t, *p_W2t;
    cudaGetSymbolAddress((void**)&p_xB,   g_xB);
    cudaGetSymbolAddress((void**)&p_xr,   g_xr);
    cudaGetSymbolAddress((void**)&p_xwh,  g_xwh);
    cudaGetSymbolAddress((void**)&p_hh,   g_hh);
    cudaGetSymbolAddress((void**)&p_l2h,  g_l2h);
    cudaGetSymbolAddress((void**)&p_hidh, g_hidh);
    cudaGetSymbolAddress((void**)&p_Bmt,  g_Bmt);
    cudaGetSymbolAddress((void**)&p_Cmt,  g_Cmt);
    cudaGetSymbolAddress((void**)&p_At,   g_At);
    cudaGetSymbolAddress((void**)&p_W1t,  g_W1t);
    cudaGetSymbolAddress((void**)&p_W2t,  g_W2t);

    cudaFuncSetAttribute(scan_mma, cudaFuncAttributeMaxDynamicSharedMemorySize, SCAN_SMEM);
    cudaFuncSetAttribute(gemm_h<EPI_NONE>,    cudaFuncAttributeMaxDynamicSharedMemorySize, GEMM_SMEM);
    cudaFuncSetAttribute(gemm_h<EPI_WINREV>,  cudaFuncAttributeMaxDynamicSharedMemorySize, GEMM_SMEM);
    cudaFuncSetAttribute(gemm_h<EPI_GELU>,    cudaFuncAttributeMaxDynamicSharedMemorySize, GEMM_SMEM);
    cudaFuncSetAttribute(gemm_h<EPI_BIASRES>, cudaFuncAttributeMaxDynamicSharedMemorySize, GEMM_SMEM);

    // 0. weight transposes -> half [N][K]
    transpose_h<<<dim3(DIM / 32, DIM / 32), 256>>>(Bm, p_Bmt, DIM, DIM);
    transpose_h<<<dim3(DIM / 32, DIM / 32), 256>>>(Cm, p_Cmt, DIM, DIM);
    transpose_h<<<dim3(DIM / 32, DIM / 32), 256>>>(A,  p_At,  DIM, DIM);
    transpose_h<<<dim3(HID / 32, DIM / 32), 256>>>(W1, p_W1t, DIM, HID);
    transpose_h<<<dim3(DIM / 32, HID / 32), 256>>>(W2, p_W2t, HID, DIM);

    // 1. LN1 + window partition -> half
    ln_kernel<<<MTOK / 8, 256>>>(x, ln1w, ln1b, p_xwh, 1);

    // 2. xB = xw @ Bm  (fp32 out, scan input)
    gemm_h<EPI_NONE><<<dim3(DIM / 128, MTOK / 128), 256, GEMM_SMEM>>>(p_xwh, p_Bmt, nullptr, nullptr, p_xB, MTOK, DIM, DIM);

    // 3. tensor-core sequential scan -> half states
    scan_mma<<<NWIN / 16, 256, SCAN_SMEM>>>(p_xB, p_At, p_hh);

    // 4. xr = h @ Cm, fused window-reverse (fp32 out)
    gemm_h<EPI_WINREV><<<dim3(DIM / 128, MTOK / 128), 256, GEMM_SMEM>>>(p_hh, p_Cmt, nullptr, nullptr, p_xr, MTOK, DIM, DIM);

    // 5. LN2 -> half
    ln_kernel<<<MTOK / 8, 256>>>(p_xr, ln2w, ln2b, p_l2h, 0);

    // 6. hid = gelu(ln2 @ W1 + b1) -> half
    gemm_h<EPI_GELU><<<dim3(HID / 128, MTOK / 128), 256, GEMM_SMEM>>>(p_l2h, p_W1t, b1, nullptr, p_hidh, MTOK, HID, DIM);

    // 7. out = xr + hid @ W2 + b2 (fp32)
    gemm_h<EPI_BIASRES><<<dim3(DIM / 128, MTOK / 128), 256, GEMM_SMEM>>>(p_hidh, p_W2t, b2, p_xr, out, MTOK, DIM, HID);
}

// round 13
// speedup vs baseline: 6.5882x; 1.0921x over previous
#include <cuda_runtime.h>
#include <cuda_fp16.h>
#include <cstdint>
#include <math.h>

// ---------------- problem constants ----------------
#define BATCH   16
#define HH      56
#define WW      56
#define DIM     384
#define HID     1536
#define WS      7
#define NWIN    1024
#define TSEQ    49
#define MTOK    50176
#define LN_EPS  1e-5f

// ---------------- device scratch ----------------
__device__ __align__(16) float  g_xB  [ (size_t)MTOK * DIM ];
__device__ __align__(16) float  g_xr  [ (size_t)MTOK * DIM ];
__device__ __align__(16) __half g_xwh [ (size_t)MTOK * DIM ];
__device__ __align__(16) __half g_hh  [ (size_t)MTOK * DIM ];
__device__ __align__(16) __half g_l2h [ (size_t)MTOK * DIM ];
__device__ __align__(16) __half g_hidh[ (size_t)MTOK * HID ];
__device__ __align__(16) __half g_Bmt [ DIM * DIM ];
__device__ __align__(16) __half g_Cmt [ DIM * DIM ];
__device__ __align__(16) __half g_At  [ DIM * DIM ];   // A^T [n][k] half
__device__ __align__(16) __half g_W1t [ (size_t)HID * DIM ];
__device__ __align__(16) __half g_W2t [ (size_t)DIM * HID ];

// ---------------- transpose + fp32->fp16 for weights ----------------
__global__ __launch_bounds__(256)
void transpose_h(const float* __restrict__ W, __half* __restrict__ Wt, int K, int N)
{
    __shared__ float tile[32][33];
    const int k0 = blockIdx.y * 32, n0 = blockIdx.x * 32;
    const int tx = threadIdx.x & 31, ty = threadIdx.x >> 5;
#pragma unroll
    for (int i = 0; i < 32; i += 8)
        tile[ty + i][tx] = W[(size_t)(k0 + ty + i) * N + n0 + tx];
    __syncthreads();
#pragma unroll
    for (int i = 0; i < 32; i += 8)
        Wt[(size_t)(n0 + ty + i) * K + k0 + tx] = __float2half_rn(tile[tx][ty + i]);
}

// ---------------- LayerNorm (warp per token) -> half, optional window remap ----------------
__global__ __launch_bounds__(256)
void ln_kernel(const float* __restrict__ x, const float* __restrict__ gw,
               const float* __restrict__ gb, __half* __restrict__ out, int remap)
{
    const int warp = threadIdx.x >> 5;
    const int lane = threadIdx.x & 31;
    const int token = blockIdx.x * 8 + warp;

    const float4* row = reinterpret_cast<const float4*>(x + (size_t)token * DIM);
    float4 v[3];
    float sum = 0.f, sq = 0.f;
#pragma unroll
    for (int q = 0; q < 3; q++) {
        v[q] = row[lane + 32 * q];
        sum += v[q].x + v[q].y + v[q].z + v[q].w;
        sq  += v[q].x * v[q].x + v[q].y * v[q].y + v[q].z * v[q].z + v[q].w * v[q].w;
    }
#pragma unroll
    for (int o = 16; o > 0; o >>= 1) {
        sum += __shfl_xor_sync(0xffffffffu, sum, o);
        sq  += __shfl_xor_sync(0xffffffffu, sq, o);
    }
    const float mu  = sum * (1.f / DIM);
    const float inv = rsqrtf(sq * (1.f / DIM) - mu * mu + LN_EPS);

    int orow = token;
    if (remap) {
        const int b   = token / (HH * WW);
        const int rem = token - b * (HH * WW);
        const int h   = rem / WW;
        const int w   = rem - h * WW;
        const int n   = b * 64 + (h / WS) * 8 + (w / WS);
        const int t   = (h % WS) * WS + (w % WS);
        orow = n * TSEQ + t;
    }
    __half* op = out + (size_t)orow * DIM;
    const float4* gw4 = reinterpret_cast<const float4*>(gw);
    const float4* gb4 = reinterpret_cast<const float4*>(gb);
#pragma unroll
    for (int q = 0; q < 3; q++) {
        const int c4 = lane + 32 * q;
        const float4 wv = gw4[c4];
        const float4 bv = gb4[c4];
        float rx = (v[q].x - mu) * inv * wv.x + bv.x;
        float ry = (v[q].y - mu) * inv * wv.y + bv.y;
        float rz = (v[q].z - mu) * inv * wv.z + bv.z;
        float rw = (v[q].w - mu) * inv * wv.w + bv.w;
        *reinterpret_cast<__half2*>(op + c4 * 4)     = __floats2half2_rn(rx, ry);
        *reinterpret_cast<__half2*>(op + c4 * 4 + 2) = __floats2half2_rn(rz, rw);
    }
}

// ---------------- MMA helpers ----------------
__device__ __forceinline__ void ldsm_x4(uint32_t& r0, uint32_t& r1, uint32_t& r2, uint32_t& r3, uint32_t addr)
{
    asm volatile("ldmatrix.sync.aligned.m8n8.x4.shared.b16 {%0,%1,%2,%3}, [%4];"
                 : "=r"(r0), "=r"(r1), "=r"(r2), "=r"(r3) : "r"(addr));
}
__device__ __forceinline__ void ldsm_x2(uint32_t& r0, uint32_t& r1, uint32_t addr)
{
    asm volatile("ldmatrix.sync.aligned.m8n8.x2.shared.b16 {%0,%1}, [%2];"
                 : "=r"(r0), "=r"(r1) : "r"(addr));
}
__device__ __forceinline__ void mma16816(float& c0, float& c1, float& c2, float& c3,
                                         uint32_t a0, uint32_t a1, uint32_t a2, uint32_t a3,
                                         uint32_t b0, uint32_t b1)
{
    asm volatile("mma.sync.aligned.m16n8k16.row.col.f32.f16.f16.f32 "
                 "{%0,%1,%2,%3}, {%4,%5,%6,%7}, {%8,%9}, {%0,%1,%2,%3};"
                 : "+f"(c0), "+f"(c1), "+f"(c2), "+f"(c3)
                 : "r"(a0), "r"(a1), "r"(a2), "r"(a3), "r"(b0), "r"(b1));
}
__device__ __forceinline__ void cp_async16(uint32_t dst, const void* src)
{
    asm volatile("cp.async.cg.shared.global [%0], [%1], 16;" :: "r"(dst), "l"(src));
}
__device__ __forceinline__ void cp_commit()
{
    asm volatile("cp.async.commit_group;");
}
template<int N> __device__ __forceinline__ void cp_wait()
{
    asm volatile("cp.async.wait_group %0;" :: "n"(N));
}

// ---------------- tensor-core scan: h_t = xB_t + h_{t-1} @ A ----------------
#define SPITCH 72
#define SBUFH  (DIM * SPITCH)
#define HPITCH 392
#define SCAN_SMEM ((3 * SBUFH + 16 * HPITCH) * 2)

__global__ __launch_bounds__(256)
void scan_mma(const float* __restrict__ xB, const __half* __restrict__ At,
              __half* __restrict__ hout)
{
    extern __shared__ __half smem[];
    __half* sH = smem + 3 * SBUFH;

    const int tid  = threadIdx.x;
    const int lane = tid & 31;
    const int wn   = tid >> 5;
    const int gr   = lane >> 2, tg = lane & 3;
    const int n0   = blockIdx.x * 16;

    const uint32_t sAbase = (uint32_t)__cvta_generic_to_shared(smem);
    const uint32_t sHbase = (uint32_t)__cvta_generic_to_shared(sH);

    const uint32_t hOff = (uint32_t)(((((lane >> 3) & 1) * 8 + (lane & 7)) * HPITCH + (lane >> 4) * 8) * 2);
    const uint32_t bOff = (uint32_t)(((wn * 48 + (lane & 7)) * SPITCH + ((lane >> 3) & 1) * 8) * 2);

    const int colb = wn * 48 + tg * 2;
    const int w0 = n0 + gr, w1 = n0 + gr + 8;
    const float* xB0 = xB + (size_t)w0 * TSEQ * DIM;
    const float* xB1 = xB + (size_t)w1 * TSEQ * DIM;
    __half* ho0 = hout + (size_t)w0 * TSEQ * DIM;
    __half* ho1 = hout + (size_t)w1 * TSEQ * DIM;

    auto issue = [&](int c, int b) {
        const uint32_t dbase = sAbase + (uint32_t)b * (SBUFH * 2);
#pragma unroll
        for (int i = 0; i < 12; i++) {
            const int idx = i * 256 + tid;
            const int row = idx >> 3, seg = idx & 7;
            cp_async16(dbase + (uint32_t)(row * SPITCH + seg * 8) * 2,
                       At + (size_t)row * DIM + c * 64 + seg * 8);
        }
        cp_commit();
    };

    issue(0, 0);
    issue(1, 1);
    int nxt = 2;

    float acc[6][4];

#pragma unroll
    for (int ni = 0; ni < 6; ni++) {
        const float2 a = *reinterpret_cast<const float2*>(xB0 + colb + ni * 8);
        const float2 b = *reinterpret_cast<const float2*>(xB1 + colb + ni * 8);
        acc[ni][0] = a.x; acc[ni][1] = a.y; acc[ni][2] = b.x; acc[ni][3] = b.y;
        const __half2 h0 = __floats2half2_rn(a.x, a.y);
        const __half2 h1 = __floats2half2_rn(b.x, b.y);
        *reinterpret_cast<__half2*>(&sH[gr * HPITCH + colb + ni * 8])       = h0;
        *reinterpret_cast<__half2*>(&sH[(gr + 8) * HPITCH + colb + ni * 8]) = h1;
        *reinterpret_cast<__half2*>(ho0 + colb + ni * 8) = h0;
        *reinterpret_cast<__half2*>(ho1 + colb + ni * 8) = h1;
    }

    for (int t = 1; t < TSEQ; t++) {
#pragma unroll
        for (int ni = 0; ni < 6; ni++) {
            const float2 a = *reinterpret_cast<const float2*>(xB0 + (size_t)t * DIM + colb + ni * 8);
            const float2 b = *reinterpret_cast<const float2*>(xB1 + (size_t)t * DIM + colb + ni * 8);
            acc[ni][0] = a.x; acc[ni][1] = a.y; acc[ni][2] = b.x; acc[ni][3] = b.y;
        }

        for (int cc = 0; cc < 6; cc++) {
            const int cur = nxt - 2;
            cp_wait<1>();
            __syncthreads();
            issue(nxt % 6, nxt % 3);
            nxt++;
            const uint32_t bufB = sAbase + (uint32_t)(cur % 3) * (SBUFH * 2) + bOff;
#pragma unroll
            for (int kt = 0; kt < 4; kt++) {
                uint32_t a0, a1, a2, a3;
                ldsm_x4(a0, a1, a2, a3, sHbase + hOff + (uint32_t)(cc * 4 + kt) * 32);
#pragma unroll
                for (int ni = 0; ni < 6; ni++) {
                    uint32_t b0, b1;
                    ldsm_x2(b0, b1, bufB + (uint32_t)(ni * 8 * SPITCH * 2) + (uint32_t)kt * 32);
                    mma16816(acc[ni][0], acc[ni][1], acc[ni][2], acc[ni][3],
                             a0, a1, a2, a3, b0, b1);
                }
            }
        }
        __syncthreads();
#pragma unroll
        for (int ni = 0; ni < 6; ni++) {
            const __half2 h0 = __floats2half2_rn(acc[ni][0], acc[ni][1]);
            const __half2 h1 = __floats2half2_rn(acc[ni][2], acc[ni][3]);
            if (t + 1 < TSEQ) {
                *reinterpret_cast<__half2*>(&sH[gr * HPITCH + colb + ni * 8])       = h0;
                *reinterpret_cast<__half2*>(&sH[(gr + 8) * HPITCH + colb + ni * 8]) = h1;
            }
            *reinterpret_cast<__half2*>(ho0 + (size_t)t * DIM + colb + ni * 8) = h0;
            *reinterpret_cast<__half2*>(ho1 + (size_t)t * DIM + colb + ni * 8) = h1;
        }
    }
    cp_wait<0>();
}

// ---------------- fp16 tensor-core GEMM, cp.async 3-stage pipeline, BK=64 ----------------
// C[M,N] = A[M,K] @ Bt[N,K]^T.  128x128 CTA tile, 8 warps 4x2.
#define EPI_NONE    0
#define EPI_WINREV  1
#define EPI_GELU    2
#define EPI_BIASRES 3

#define GP     72                     // halfs per smem row (64 + 8 pad)
#define GSTGH  (128 * GP)             // halfs per operand per stage
#define GEMM_SMEM (3 * 2 * GSTGH * 2) // 3 stages x (A+B) = 110592 bytes

__device__ __forceinline__ float gelu_exact(float v)
{
    return 0.5f * v * (1.f + erff(v * 0.70710678118654752f));
}

template<int EPI>
__global__ __launch_bounds__(256)
void gemm_h(const __half* __restrict__ Ag, const __half* __restrict__ Bg,
            const float* __restrict__ bias, const float* __restrict__ res,
            void* __restrict__ Cv, int M, int N, int K)
{
    extern __shared__ __align__(16) __half gsm[];

    const int tid  = threadIdx.x;
    const int lane = tid & 31;
    const int wid  = tid >> 5;
    const int wm   = wid >> 1;          // 0..3
    const int wn   = wid & 1;           // 0..1
    const int m0   = blockIdx.y * 128;
    const int n0   = blockIdx.x * 128;

    const uint32_t smB = (uint32_t)__cvta_generic_to_shared(gsm);

    // staging: per stage per operand 128 rows x 64 halfs = 1024 x 16B chunks;
    // thread covers chunks tid, tid+256, tid+512, tid+768.
    const int rr[4] = { tid >> 3, (tid + 256) >> 3, (tid + 512) >> 3, (tid + 768) >> 3 };
    const int ss[4] = { tid & 7,  (tid + 256) & 7,  (tid + 512) & 7,  (tid + 768) & 7 };

    auto load_stage = [&](int kt, int stg) {
        const uint32_t base = smB + (uint32_t)stg * (2 * GSTGH * 2);
        const size_t ko = (size_t)kt * 64;
#pragma unroll
        for (int i = 0; i < 4; i++) {
            const uint32_t so = (uint32_t)(rr[i] * GP + ss[i] * 8) * 2;
            cp_async16(base + so,             Ag + (size_t)(m0 + rr[i]) * K + ko + ss[i] * 8);
            cp_async16(base + GSTGH * 2 + so, Bg + (size_t)(n0 + rr[i]) * K + ko + ss[i] * 8);
        }
        cp_commit();
    };

    // ldmatrix lane addresses (byte offsets within a stage)
    const uint32_t aOff = (uint32_t)(((wm * 32 + ((lane >> 3) & 1) * 8 + (lane & 7)) * GP + (lane >> 4) * 8) * 2);
    const uint32_t bOff = (uint32_t)(((wn * 64 + ((lane >> 4) & 1) * 8 + (lane & 7)) * GP + ((lane >> 3) & 1) * 8) * 2);

    float acc[2][8][4];
#pragma unroll
    for (int mi = 0; mi < 2; mi++)
#pragma unroll
        for (int ni = 0; ni < 8; ni++)
#pragma unroll
            for (int q = 0; q < 4; q++) acc[mi][ni][q] = 0.f;

    const int NK = K >> 6;            // k-tiles of 64
    load_stage(0, 0);
    load_stage(1, 1);

    for (int kt = 0; kt < NK; kt++) {
        if (kt + 1 < NK) cp_wait<1>(); else cp_wait<0>();
        __syncthreads();
        if (kt + 2 < NK) load_stage(kt + 2, (kt + 2) % 3);

        const uint32_t stgB = smB + (uint32_t)(kt % 3) * (2 * GSTGH * 2);
        const uint32_t aB = stgB + aOff;
        const uint32_t bB = stgB + GSTGH * 2 + bOff;
#pragma unroll
        for (int kk = 0; kk < 4; kk++) {           // 4 x k16
            uint32_t a[2][4], bf[8][2];
            ldsm_x4(a[0][0], a[0][1], a[0][2], a[0][3], aB + kk * 32);
            ldsm_x4(a[1][0], a[1][1], a[1][2], a[1][3], aB + kk * 32 + 16 * GP * 2);
#pragma unroll
            for (int nj = 0; nj < 4; nj++)
                ldsm_x4(bf[nj * 2][0], bf[nj * 2][1], bf[nj * 2 + 1][0], bf[nj * 2 + 1][1],
                        bB + kk * 32 + (uint32_t)(nj * 16 * GP * 2));
#pragma unroll
            for (int mi = 0; mi < 2; mi++)
#pragma unroll
                for (int ni = 0; ni < 8; ni++)
                    mma16816(acc[mi][ni][0], acc[mi][ni][1], acc[mi][ni][2], acc[mi][ni][3],
                             a[mi][0], a[mi][1], a[mi][2], a[mi][3], bf[ni][0], bf[ni][1]);
        }
    }

    // ---------------- epilogue ----------------
    const int gr = lane >> 2, tg = lane & 3;

    float2 bias2[8];
    if (EPI == EPI_GELU || EPI == EPI_BIASRES) {
#pragma unroll
        for (int ni = 0; ni < 8; ni++)
            bias2[ni] = *reinterpret_cast<const float2*>(bias + n0 + wn * 64 + ni * 8 + tg * 2);
    }

#pragma unroll
    for (int mi = 0; mi < 2; mi++)
#pragma unroll
    for (int rh = 0; rh < 2; rh++) {
        const int gm = m0 + wm * 32 + mi * 16 + rh * 8 + gr;
        int orow = gm;
        if (EPI == EPI_WINREV) {
            const int n = gm / TSEQ;
            const int t = gm - n * TSEQ;
            const int b = n >> 6;
            const int rm = n & 63;
            const int wh = rm >> 3, wwi = rm & 7;
            const int ti = t / WS, tj = t - ti * WS;
            orow = (b * HH + wh * WS + ti) * WW + wwi * WS + tj;
        }
#pragma unroll
        for (int ni = 0; ni < 8; ni++) {
            const int col = n0 + wn * 64 + ni * 8 + tg * 2;
            float v0 = acc[mi][ni][rh * 2];
            float v1 = acc[mi][ni][rh * 2 + 1];
            if (EPI == EPI_GELU) {
                v0 = gelu_exact(v0 + bias2[ni].x);
                v1 = gelu_exact(v1 + bias2[ni].y);
                __half* C = (__half*)Cv;
                *reinterpret_cast<__half2*>(C + (size_t)orow * N + col) = __floats2half2_rn(v0, v1);
            } else {
                if (EPI == EPI_BIASRES) {
                    const float2 r = *reinterpret_cast<const float2*>(res + (size_t)gm * N + col);
                    v0 += bias2[ni].x + r.x;
                    v1 += bias2[ni].y + r.y;
                }
                float* C = (float*)Cv;
                float2 o; o.x = v0; o.y = v1;
                *reinterpret_cast<float2*>(C + (size_t)orow * N + col) = o;
            }
        }
    }
}

// ---------------- launch ----------------
extern "C" void kernel_launch(void* const* d_in, const int* in_sizes, int n_in,
                              void* d_out, int out_size)
{
    const float* x    = (const float*)d_in[0];
    const float* A    = (const float*)d_in[1];
    const float* Bm   = (const float*)d_in[2];
    const float* Cm   = (const float*)d_in[3];
    const float* ln1w = (const float*)d_in[4];
    const float* ln1b = (const float*)d_in[5];
    const float* ln2w = (const float*)d_in[6];
    const float* ln2b = (const float*)d_in[7];
    const float* W1   = (const float*)d_in[8];
    const float* b1   = (const float*)d_in[9];
    const float* W2   = (const float*)d_in[10];
    const float* b2   = (const float*)d_in[11];
    float* out = (float*)d_out;

    float  *p_xB, *p_xr;
    __half *p_xwh, *p_hh, *p_l2h, *p_hidh, *p_Bmt, *p_Cmt, *p_At, *p_W1t, *p_W2t;
    cudaGetSymbolAddress((void**)&p_xB,   g_xB);
    cudaGetSymbolAddress((void**)&p_xr,   g_xr);
    cudaGetSymbolAddress((void**)&p_xwh,  g_xwh);
    cudaGetSymbolAddress((void**)&p_hh,   g_hh);
    cudaGetSymbolAddress((void**)&p_l2h,  g_l2h);
    cudaGetSymbolAddress((void**)&p_hidh, g_hidh);
    cudaGetSymbolAddress((void**)&p_Bmt,  g_Bmt);
    cudaGetSymbolAddress((void**)&p_Cmt,  g_Cmt);
    cudaGetSymbolAddress((void**)&p_At,   g_At);
    cudaGetSymbolAddress((void**)&p_W1t,  g_W1t);
    cudaGetSymbolAddress((void**)&p_W2t,  g_W2t);

    cudaFuncSetAttribute(scan_mma, cudaFuncAttributeMaxDynamicSharedMemorySize, SCAN_SMEM);
    cudaFuncSetAttribute(gemm_h<EPI_NONE>,    cudaFuncAttributeMaxDynamicSharedMemorySize, GEMM_SMEM);
    cudaFuncSetAttribute(gemm_h<EPI_WINREV>,  cudaFuncAttributeMaxDynamicSharedMemorySize, GEMM_SMEM);
    cudaFuncSetAttribute(gemm_h<EPI_GELU>,    cudaFuncAttributeMaxDynamicSharedMemorySize, GEMM_SMEM);
    cudaFuncSetAttribute(gemm_h<EPI_BIASRES>, cudaFuncAttributeMaxDynamicSharedMemorySize, GEMM_SMEM);

    // launches 0-4: 4 weight transposes + LN1  (so launch #5 = GEMM1 for ncu -s 5)
    transpose_h<<<dim3(DIM / 32, DIM / 32), 256>>>(Bm, p_Bmt, DIM, DIM);
    transpose_h<<<dim3(DIM / 32, DIM / 32), 256>>>(Cm, p_Cmt, DIM, DIM);
    transpose_h<<<dim3(HID / 32, DIM / 32), 256>>>(W1, p_W1t, DIM, HID);
    transpose_h<<<dim3(DIM / 32, HID / 32), 256>>>(W2, p_W2t, HID, DIM);
    ln_kernel<<<MTOK / 8, 256>>>(x, ln1w, ln1b, p_xwh, 1);

    // launch 5: xB = xw @ Bm  (fp32 out, scan input)
    gemm_h<EPI_NONE><<<dim3(DIM / 128, MTOK / 128), 256, GEMM_SMEM>>>(p_xwh, p_Bmt, nullptr, nullptr, p_xB, MTOK, DIM, DIM);

    // A^T transpose (only needed by scan)
    transpose_h<<<dim3(DIM / 32, DIM / 32), 256>>>(A,  p_At,  DIM, DIM);

    // tensor-core sequential scan -> half states
    scan_mma<<<NWIN / 16, 256, SCAN_SMEM>>>(p_xB, p_At, p_hh);

    // xr = h @ Cm, fused window-reverse (fp32 out)
    gemm_h<EPI_WINREV><<<dim3(DIM / 128, MTOK / 128), 256, GEMM_SMEM>>>(p_hh, p_Cmt, nullptr, nullptr, p_xr, MTOK, DIM, DIM);

    // LN2 -> half
    ln_kernel<<<MTOK / 8, 256>>>(p_xr, ln2w, ln2b, p_l2h, 0);

    // hid = gelu(ln2 @ W1 + b1) -> half
    gemm_h<EPI_GELU><<<dim3(HID / 128, MTOK / 128), 256, GEMM_SMEM>>>(p_l2h, p_W1t, b1, nullptr, p_hidh, MTOK, HID, DIM);

    // out = xr + hid @ W2 + b2 (fp32)
    gemm_h<EPI_BIASRES><<<dim3(DIM / 128, MTOK / 128), 256, GEMM_SMEM>>>(p_hidh, p_W2t, b2, p_xr, out, MTOK, DIM, HID);
}